// round 12
// baseline (speedup 1.0000x reference)
#include <cuda_runtime.h>
#include <cuda_bf16.h>
#include <mma.h>
#include <float.h>

using namespace nvcuda;

#define BB 16
#define CL 512
#define QL 64
#define HH 768
#define NEG_INF (-1e30f)

typedef __nv_bfloat16 bf16;

// ---------------- scratch ----------------
__device__ __align__(16) float g_qp[BB * QL * HH];    // q @ W            [B,64,768]
__device__ __align__(16) float g_bq[BB * QL];         // q . b            [B,64]
__device__ __align__(16) float g_s [BB * CL * QL];    // raw logits       [B,512,64]
__device__ __align__(16) float g_s2[BB * CL * QL];    // col exp (unnorm) [B,512,64]
__device__ __align__(16) float g_cinv[BB * QL];       // 1/col-sum        [B,64]
__device__ __align__(16) bf16  g_s1h[BB * CL * QL];   // s1 hi            [B,512,64]
__device__ __align__(16) bf16  g_s1l[BB * CL * QL];   // s1 lo
__device__ __align__(16) bf16  g_qh[BB * QL * HH];    // q hi             [B,64,768]
__device__ __align__(16) bf16  g_ql[BB * QL * HH];    // q lo
__device__ __align__(16) bf16  g_th[BB * QL * HH];    // t hi             [B,64,768]
__device__ __align__(16) bf16  g_tl[BB * QL * HH];    // t lo

__device__ __forceinline__ void split_bf16(float x, bf16& h, bf16& l) {
    h = __float2bfloat16_rn(x);
    l = __float2bfloat16_rn(x - __bfloat162float(h));
}

// ---------------- bq[row] = q[row,:] . b ----------------
__global__ void bq_kernel(const float* __restrict__ q, const float* __restrict__ bias) {
    int row  = blockIdx.x * 8 + (threadIdx.x >> 5);
    int lane = threadIdx.x & 31;
    const float* qr = q + row * HH;
    float s = 0.f;
    for (int d = lane; d < HH; d += 32) s += qr[d] * bias[d];
#pragma unroll
    for (int o = 16; o; o >>= 1) s += __shfl_down_sync(0xffffffffu, s, o);
    if (lane == 0) g_bq[row] = s;
}

// ---------------- q -> bf16 hi/lo split ----------------
__global__ void qsplit_kernel(const float* __restrict__ q) {
    int idx = (blockIdx.x * 256 + threadIdx.x) * 4;   // 786432 elems, 768 blocks
    float4 v = *(const float4*)(q + idx);
    bf16 h0, l0, h1, l1, h2, l2, h3, l3;
    split_bf16(v.x, h0, l0); split_bf16(v.y, h1, l1);
    split_bf16(v.z, h2, l2); split_bf16(v.w, h3, l3);
    *(__nv_bfloat162*)(g_qh + idx)     = __nv_bfloat162(h0, h1);
    *(__nv_bfloat162*)(g_qh + idx + 2) = __nv_bfloat162(h2, h3);
    *(__nv_bfloat162*)(g_ql + idx)     = __nv_bfloat162(l0, l1);
    *(__nv_bfloat162*)(g_ql + idx + 2) = __nv_bfloat162(l2, l3);
}

// ---------------- qp = q @ W   (M=1024, N=768, K=768) ----------------
__global__ void qp_gemm(const float* __restrict__ q, const float* __restrict__ W) {
    __shared__ __align__(16) float As[2][16][68];
    __shared__ __align__(16) float Bs[2][16][68];
    int tid = threadIdx.x;
    int tx = tid & 15, ty = tid >> 4;
    int tx4 = tx << 2, ty4 = ty << 2;
    int mBase = blockIdx.y * 64, nBase = blockIdx.x * 64;
    int lm = tid >> 2, lk = (tid & 3) << 2;
    int bk = tid >> 4, bn4 = (tid & 15) << 2;
    float acc[4][4] = {};

    float4 av = *(const float4*)(q + (mBase + lm) * HH + lk);
    float4 bv = *(const float4*)(W + bk * HH + nBase + bn4);
    As[0][lk + 0][lm] = av.x; As[0][lk + 1][lm] = av.y;
    As[0][lk + 2][lm] = av.z; As[0][lk + 3][lm] = av.w;
    *(float4*)&Bs[0][bk][bn4] = bv;
    __syncthreads();
    int buf = 0;
    for (int kt = 0; kt < HH; kt += 16) {
        bool more = (kt + 16) < HH;
        float4 nav, nbv;
        if (more) {
            nav = *(const float4*)(q + (mBase + lm) * HH + kt + 16 + lk);
            nbv = *(const float4*)(W + (kt + 16 + bk) * HH + nBase + bn4);
        }
#pragma unroll
        for (int k = 0; k < 16; k++) {
            float4 ar = *(const float4*)&As[buf][k][ty4];
            float4 br = *(const float4*)&Bs[buf][k][tx4];
            acc[0][0] = fmaf(ar.x, br.x, acc[0][0]); acc[0][1] = fmaf(ar.x, br.y, acc[0][1]);
            acc[0][2] = fmaf(ar.x, br.z, acc[0][2]); acc[0][3] = fmaf(ar.x, br.w, acc[0][3]);
            acc[1][0] = fmaf(ar.y, br.x, acc[1][0]); acc[1][1] = fmaf(ar.y, br.y, acc[1][1]);
            acc[1][2] = fmaf(ar.y, br.z, acc[1][2]); acc[1][3] = fmaf(ar.y, br.w, acc[1][3]);
            acc[2][0] = fmaf(ar.z, br.x, acc[2][0]); acc[2][1] = fmaf(ar.z, br.y, acc[2][1]);
            acc[2][2] = fmaf(ar.z, br.z, acc[2][2]); acc[2][3] = fmaf(ar.z, br.w, acc[2][3]);
            acc[3][0] = fmaf(ar.w, br.x, acc[3][0]); acc[3][1] = fmaf(ar.w, br.y, acc[3][1]);
            acc[3][2] = fmaf(ar.w, br.z, acc[3][2]); acc[3][3] = fmaf(ar.w, br.w, acc[3][3]);
        }
        if (more) {
            int nb = buf ^ 1;
            As[nb][lk + 0][lm] = nav.x; As[nb][lk + 1][lm] = nav.y;
            As[nb][lk + 2][lm] = nav.z; As[nb][lk + 3][lm] = nav.w;
            *(float4*)&Bs[nb][bk][bn4] = nbv;
            __syncthreads();
            buf = nb;
        }
    }
#pragma unroll
    for (int i = 0; i < 4; i++) {
        float4 o = make_float4(acc[i][0], acc[i][1], acc[i][2], acc[i][3]);
        *(float4*)(g_qp + (mBase + ty4 + i) * HH + nBase + tx4) = o;
    }
}

// ---------------- s_gemm + fused row softmax (emits bf16 hi/lo s1) ----------------
__global__ void s_gemm(const float* __restrict__ c, const int* __restrict__ q_mask) {
    __shared__ __align__(16) float As[2][16][68];
    __shared__ __align__(16) float Bs[2][16][68];
    int tid = threadIdx.x;
    int tx = tid & 15, ty = tid >> 4;
    int tx4 = tx << 2, ty4 = ty << 2;
    int b = blockIdx.y;
    int mBase = blockIdx.x * 64;
    const float* A = c + b * CL * HH;
    const float* Bt = g_qp + b * QL * HH;
    int lm = tid >> 2, lk = (tid & 3) << 2;
    float acc[4][4] = {};

    {
        float4 av = *(const float4*)(A + (mBase + lm) * HH + lk);
        float4 bv = *(const float4*)(Bt + lm * HH + lk);
        As[0][lk + 0][lm] = av.x; As[0][lk + 1][lm] = av.y;
        As[0][lk + 2][lm] = av.z; As[0][lk + 3][lm] = av.w;
        Bs[0][lk + 0][lm] = bv.x; Bs[0][lk + 1][lm] = bv.y;
        Bs[0][lk + 2][lm] = bv.z; Bs[0][lk + 3][lm] = bv.w;
    }
    __syncthreads();
    int buf = 0;
    for (int kt = 0; kt < HH; kt += 16) {
        bool more = (kt + 16) < HH;
        float4 nav, nbv;
        if (more) {
            nav = *(const float4*)(A + (mBase + lm) * HH + kt + 16 + lk);
            nbv = *(const float4*)(Bt + lm * HH + kt + 16 + lk);
        }
#pragma unroll
        for (int k = 0; k < 16; k++) {
            float4 ar = *(const float4*)&As[buf][k][ty4];
            float4 br = *(const float4*)&Bs[buf][k][tx4];
            acc[0][0] = fmaf(ar.x, br.x, acc[0][0]); acc[0][1] = fmaf(ar.x, br.y, acc[0][1]);
            acc[0][2] = fmaf(ar.x, br.z, acc[0][2]); acc[0][3] = fmaf(ar.x, br.w, acc[0][3]);
            acc[1][0] = fmaf(ar.y, br.x, acc[1][0]); acc[1][1] = fmaf(ar.y, br.y, acc[1][1]);
            acc[1][2] = fmaf(ar.y, br.z, acc[1][2]); acc[1][3] = fmaf(ar.y, br.w, acc[1][3]);
            acc[2][0] = fmaf(ar.z, br.x, acc[2][0]); acc[2][1] = fmaf(ar.z, br.y, acc[2][1]);
            acc[2][2] = fmaf(ar.z, br.z, acc[2][2]); acc[2][3] = fmaf(ar.z, br.w, acc[2][3]);
            acc[3][0] = fmaf(ar.w, br.x, acc[3][0]); acc[3][1] = fmaf(ar.w, br.y, acc[3][1]);
            acc[3][2] = fmaf(ar.w, br.z, acc[3][2]); acc[3][3] = fmaf(ar.w, br.w, acc[3][3]);
        }
        if (more) {
            int nb = buf ^ 1;
            As[nb][lk + 0][lm] = nav.x; As[nb][lk + 1][lm] = nav.y;
            As[nb][lk + 2][lm] = nav.z; As[nb][lk + 3][lm] = nav.w;
            Bs[nb][lk + 0][lm] = nbv.x; Bs[nb][lk + 1][lm] = nbv.y;
            Bs[nb][lk + 2][lm] = nbv.z; Bs[nb][lk + 3][lm] = nbv.w;
            __syncthreads();
            buf = nb;
        }
    }
    float4 bqv = *(const float4*)(g_bq + b * QL + tx4);
    int qm0 = q_mask[b * QL + tx4 + 0];
    int qm1 = q_mask[b * QL + tx4 + 1];
    int qm2 = q_mask[b * QL + tx4 + 2];
    int qm3 = q_mask[b * QL + tx4 + 3];
#pragma unroll
    for (int i = 0; i < 4; i++) {
        float v0 = acc[i][0] + bqv.x, v1 = acc[i][1] + bqv.y;
        float v2 = acc[i][2] + bqv.z, v3 = acc[i][3] + bqv.w;
        int row = b * CL + mBase + ty4 + i;
        *(float4*)(g_s + row * QL + tx4) = make_float4(v0, v1, v2, v3);
        float m0 = qm0 ? v0 : NEG_INF;
        float m1 = qm1 ? v1 : NEG_INF;
        float m2 = qm2 ? v2 : NEG_INF;
        float m3 = qm3 ? v3 : NEG_INF;
        float mx = fmaxf(fmaxf(m0, m1), fmaxf(m2, m3));
#pragma unroll
        for (int o = 8; o; o >>= 1) mx = fmaxf(mx, __shfl_xor_sync(0xffffffffu, mx, o));
        float e0 = __expf(m0 - mx), e1 = __expf(m1 - mx);
        float e2 = __expf(m2 - mx), e3 = __expf(m3 - mx);
        float s = e0 + e1 + e2 + e3;
#pragma unroll
        for (int o = 8; o; o >>= 1) s += __shfl_xor_sync(0xffffffffu, s, o);
        float inv = 1.f / s;
        float s0 = e0 * inv, s1v = e1 * inv, s2v = e2 * inv, s3 = e3 * inv;
        bf16 h0, l0, h1, l1, h2, l2, h3, l3;
        split_bf16(s0, h0, l0); split_bf16(s1v, h1, l1);
        split_bf16(s2v, h2, l2); split_bf16(s3, h3, l3);
        *(__nv_bfloat162*)(g_s1h + row * QL + tx4)     = __nv_bfloat162(h0, h1);
        *(__nv_bfloat162*)(g_s1h + row * QL + tx4 + 2) = __nv_bfloat162(h2, h3);
        *(__nv_bfloat162*)(g_s1l + row * QL + tx4)     = __nv_bfloat162(l0, l1);
        *(__nv_bfloat162*)(g_s1l + row * QL + tx4 + 2) = __nv_bfloat162(l2, l3);
    }
}

// ---------------- colexp: per-batch column max + exp + 1/sum ----------------
__global__ void colexp_kernel(const int* __restrict__ c_mask) {
    int b  = blockIdx.x;
    int cq = blockIdx.y;
    int tid = threadIdx.x;
    int cg = tid & 3;
    int ry = tid >> 2;                   // 0..63
    int col0 = cq * 16 + cg * 4;
    __shared__ float4 red[64][4];
    const float* sp = g_s + b * CL * QL;
    const int*   mp = c_mask + b * CL;

    float4 mx = make_float4(NEG_INF, NEG_INF, NEG_INF, NEG_INF);
#pragma unroll
    for (int k = 0; k < 8; k++) {
        int r = ry + k * 64;
        float4 v = *(const float4*)(sp + r * QL + col0);
        if (!mp[r]) v = make_float4(NEG_INF, NEG_INF, NEG_INF, NEG_INF);
        mx.x = fmaxf(mx.x, v.x); mx.y = fmaxf(mx.y, v.y);
        mx.z = fmaxf(mx.z, v.z); mx.w = fmaxf(mx.w, v.w);
    }
    red[ry][cg] = mx;
    __syncthreads();
#pragma unroll
    for (int st = 32; st >= 1; st >>= 1) {
        if (ry < st) {
            float4 a = red[ry][cg], c2 = red[ry + st][cg];
            a.x = fmaxf(a.x, c2.x); a.y = fmaxf(a.y, c2.y);
            a.z = fmaxf(a.z, c2.z); a.w = fmaxf(a.w, c2.w);
            red[ry][cg] = a;
        }
        __syncthreads();
    }
    float4 cmax = red[0][cg];
    __syncthreads();

    float4 sm = make_float4(0.f, 0.f, 0.f, 0.f);
    float* op = g_s2 + b * CL * QL;
#pragma unroll
    for (int k = 0; k < 8; k++) {
        int r = ry + k * 64;
        float4 v = *(const float4*)(sp + r * QL + col0);
        if (!mp[r]) v = make_float4(NEG_INF, NEG_INF, NEG_INF, NEG_INF);
        float4 e;
        e.x = __expf(v.x - cmax.x); e.y = __expf(v.y - cmax.y);
        e.z = __expf(v.z - cmax.z); e.w = __expf(v.w - cmax.w);
        *(float4*)(op + r * QL + col0) = e;
        sm.x += e.x; sm.y += e.y; sm.z += e.z; sm.w += e.w;
    }
    red[ry][cg] = sm;
    __syncthreads();
#pragma unroll
    for (int st = 32; st >= 1; st >>= 1) {
        if (ry < st) {
            float4 a = red[ry][cg], c2 = red[ry + st][cg];
            a.x += c2.x; a.y += c2.y; a.z += c2.z; a.w += c2.w;
            red[ry][cg] = a;
        }
        __syncthreads();
    }
    if (ry == 0) {
        float4 s = red[0][cg];
        float4 inv = make_float4(1.f / s.x, 1.f / s.y, 1.f / s.z, 1.f / s.w);
        *(float4*)(g_cinv + b * QL + col0) = inv;
    }
}

// ---------------- t_gemm (emits bf16 hi/lo t) ----------------
__global__ void t_gemm(const float* __restrict__ c) {
    __shared__ __align__(16) float As[2][16][68];
    __shared__ __align__(16) float Bs[2][16][68];
    int tid = threadIdx.x;
    int tx = tid & 15, ty = tid >> 4;
    int tx4 = tx << 2, ty4 = ty << 2;
    int b = blockIdx.y;
    int nBase = blockIdx.x * 64;
    int lc = tid >> 4, lj4 = (tid & 15) << 2;
    int bk = tid >> 4, bn4 = (tid & 15) << 2;
    float4 inv4 = *(const float4*)(g_cinv + b * QL + lj4);
    float acc[4][4] = {};

    float4 av = *(const float4*)(g_s2 + (b * CL + lc) * QL + lj4);
    av.x *= inv4.x; av.y *= inv4.y; av.z *= inv4.z; av.w *= inv4.w;
    float4 bv = *(const float4*)(c + (b * CL + bk) * HH + nBase + bn4);
    *(float4*)&As[0][lc][lj4] = av;
    *(float4*)&Bs[0][bk][bn4] = bv;
    __syncthreads();
    int buf = 0;
    for (int kt = 0; kt < CL; kt += 16) {
        bool more = (kt + 16) < CL;
        float4 nav, nbv;
        if (more) {
            nav = *(const float4*)(g_s2 + (b * CL + kt + 16 + lc) * QL + lj4);
            nav.x *= inv4.x; nav.y *= inv4.y; nav.z *= inv4.z; nav.w *= inv4.w;
            nbv = *(const float4*)(c + (b * CL + kt + 16 + bk) * HH + nBase + bn4);
        }
#pragma unroll
        for (int k = 0; k < 16; k++) {
            float4 ar = *(const float4*)&As[buf][k][ty4];
            float4 br = *(const float4*)&Bs[buf][k][tx4];
            acc[0][0] = fmaf(ar.x, br.x, acc[0][0]); acc[0][1] = fmaf(ar.x, br.y, acc[0][1]);
            acc[0][2] = fmaf(ar.x, br.z, acc[0][2]); acc[0][3] = fmaf(ar.x, br.w, acc[0][3]);
            acc[1][0] = fmaf(ar.y, br.x, acc[1][0]); acc[1][1] = fmaf(ar.y, br.y, acc[1][1]);
            acc[1][2] = fmaf(ar.y, br.z, acc[1][2]); acc[1][3] = fmaf(ar.y, br.w, acc[1][3]);
            acc[2][0] = fmaf(ar.z, br.x, acc[2][0]); acc[2][1] = fmaf(ar.z, br.y, acc[2][1]);
            acc[2][2] = fmaf(ar.z, br.z, acc[2][2]); acc[2][3] = fmaf(ar.z, br.w, acc[2][3]);
            acc[3][0] = fmaf(ar.w, br.x, acc[3][0]); acc[3][1] = fmaf(ar.w, br.y, acc[3][1]);
            acc[3][2] = fmaf(ar.w, br.z, acc[3][2]); acc[3][3] = fmaf(ar.w, br.w, acc[3][3]);
        }
        if (more) {
            int nb = buf ^ 1;
            *(float4*)&As[nb][lc][lj4] = nav;
            *(float4*)&Bs[nb][bk][bn4] = nbv;
            __syncthreads();
            buf = nb;
        }
    }
#pragma unroll
    for (int i = 0; i < 4; i++) {
        int idx = (b * QL + ty4 + i) * HH + nBase + tx4;
        bf16 h0, l0, h1, l1, h2, l2, h3, l3;
        split_bf16(acc[i][0], h0, l0); split_bf16(acc[i][1], h1, l1);
        split_bf16(acc[i][2], h2, l2); split_bf16(acc[i][3], h3, l3);
        *(__nv_bfloat162*)(g_th + idx)     = __nv_bfloat162(h0, h1);
        *(__nv_bfloat162*)(g_th + idx + 2) = __nv_bfloat162(h2, h3);
        *(__nv_bfloat162*)(g_tl + idx)     = __nv_bfloat162(l0, l1);
        *(__nv_bfloat162*)(g_tl + idx + 2) = __nv_bfloat162(l2, l3);
    }
}

// ---------------- final: WMMA split-bf16. a = s1@q, bvec = s1@t ----------------
// grid (8 ctiles, 16 b, 6 z); 256 thr. 64x64 output tile per hc chunk.
// 8 warps: warp w -> rows (w&3)*16, cols (w>>2)*32 (two 16x16 acc frags).
#define LDB 80   // bf16 row stride (160 B, 32 B-aligned rows)

__global__ void final_kernel(const float* __restrict__ c, float* __restrict__ out) {
    __shared__ __align__(32) bf16 S1h[64 * LDB];
    __shared__ __align__(32) bf16 S1l[64 * LDB];
    __shared__ __align__(32) bf16 Buf2[2 * 64 * LDB];   // BufH | BufL ; aliased as fp32 stage
    bf16* BufH = Buf2;
    bf16* BufL = Buf2 + 64 * LDB;
    float* stage = (float*)Buf2;                        // 64*LDB floats = exactly BufH+BufL bytes

    int tid = threadIdx.x;
    int b = blockIdx.y;
    int cBase = blockIdx.x * 64;
    int hStart = blockIdx.z * 128;

    int lr  = tid >> 2;              // 0..63
    int lc8 = (tid & 3) << 4;        // 0,16,32,48 (col base, 16 bf16 per thread per row)

    // load s1 hi/lo tiles (64x64 bf16 each)
    {
        const bf16* sh = g_s1h + (b * CL + cBase + lr) * QL + lc8;
        const bf16* sl = g_s1l + (b * CL + cBase + lr) * QL + lc8;
        *(uint4*)(S1h + lr * LDB + lc8)     = *(const uint4*)(sh);
        *(uint4*)(S1h + lr * LDB + lc8 + 8) = *(const uint4*)(sh + 8);
        *(uint4*)(S1l + lr * LDB + lc8)     = *(const uint4*)(sl);
        *(uint4*)(S1l + lr * LDB + lc8 + 8) = *(const uint4*)(sl + 8);
    }

    int wid = tid >> 5;
    int wr = (wid & 3) * 16;         // warp row base
    int wc = (wid >> 2) * 32;        // warp col base

    const float* cb = c + b * CL * HH;
    float* ob = out + (size_t)(b * CL) * (4 * HH);

    for (int hc = hStart; hc < hStart + 128; hc += 64) {
        // ================= pass 1: a = s1 @ q =================
        __syncthreads();   // protect Buf2 (stage) from previous readers
        {
            const bf16* qh = g_qh + (b * QL + lr) * HH + hc + lc8;
            const bf16* ql = g_ql + (b * QL + lr) * HH + hc + lc8;
            *(uint4*)(BufH + lr * LDB + lc8)     = *(const uint4*)(qh);
            *(uint4*)(BufH + lr * LDB + lc8 + 8) = *(const uint4*)(qh + 8);
            *(uint4*)(BufL + lr * LDB + lc8)     = *(const uint4*)(ql);
            *(uint4*)(BufL + lr * LDB + lc8 + 8) = *(const uint4*)(ql + 8);
        }
        __syncthreads();
        {
            wmma::fragment<wmma::accumulator, 16, 16, 16, float> acc0, acc1;
            wmma::fill_fragment(acc0, 0.f);
            wmma::fill_fragment(acc1, 0.f);
#pragma unroll
            for (int ks = 0; ks < 4; ks++) {
                int k0 = ks * 16;
                wmma::fragment<wmma::matrix_a, 16, 16, 16, bf16, wmma::row_major> ah, al;
                wmma::load_matrix_sync(ah, S1h + wr * LDB + k0, LDB);
                wmma::load_matrix_sync(al, S1l + wr * LDB + k0, LDB);
                wmma::fragment<wmma::matrix_b, 16, 16, 16, bf16, wmma::row_major> bh0, bl0, bh1, bl1;
                wmma::load_matrix_sync(bh0, BufH + k0 * LDB + wc, LDB);
                wmma::load_matrix_sync(bl0, BufL + k0 * LDB + wc, LDB);
                wmma::load_matrix_sync(bh1, BufH + k0 * LDB + wc + 16, LDB);
                wmma::load_matrix_sync(bl1, BufL + k0 * LDB + wc + 16, LDB);
                wmma::mma_sync(acc0, ah, bh0, acc0);
                wmma::mma_sync(acc0, ah, bl0, acc0);
                wmma::mma_sync(acc0, al, bh0, acc0);
                wmma::mma_sync(acc1, ah, bh1, acc1);
                wmma::mma_sync(acc1, ah, bl1, acc1);
                wmma::mma_sync(acc1, al, bh1, acc1);
            }
            __syncthreads();   // all warps done reading Buf before stage overwrite
            wmma::store_matrix_sync(stage + wr * LDB + wc, acc0, LDB, wmma::mem_row_major);
            wmma::store_matrix_sync(stage + wr * LDB + wc + 16, acc1, LDB, wmma::mem_row_major);
        }
        __syncthreads();
        // epilogue pass1: write c, a, c*a
        {
            int lcb = (tid & 3) << 2;
            int r = cBase + lr;
            float* orow = ob + (size_t)r * (4 * HH);
#pragma unroll
            for (int i = 0; i < 4; i++) {
                int col = lcb + i * 16;
                float4 a4 = *(const float4*)(stage + lr * LDB + col);
                float4 cv = *(const float4*)(cb + r * HH + hc + col);
                float4 ca = make_float4(cv.x * a4.x, cv.y * a4.y, cv.z * a4.z, cv.w * a4.w);
                *(float4*)(orow + 0 * HH + hc + col) = cv;
                *(float4*)(orow + 1 * HH + hc + col) = a4;
                *(float4*)(orow + 2 * HH + hc + col) = ca;
            }
        }
        // ================= pass 2: bvec = s1 @ t =================
        __syncthreads();   // stage reads done before Buf refill
        {
            const bf16* th = g_th + (b * QL + lr) * HH + hc + lc8;
            const bf16* tl = g_tl + (b * QL + lr) * HH + hc + lc8;
            *(uint4*)(BufH + lr * LDB + lc8)     = *(const uint4*)(th);
            *(uint4*)(BufH + lr * LDB + lc8 + 8) = *(const uint4*)(th + 8);
            *(uint4*)(BufL + lr * LDB + lc8)     = *(const uint4*)(tl);
            *(uint4*)(BufL + lr * LDB + lc8 + 8) = *(const uint4*)(tl + 8);
        }
        __syncthreads();
        {
            wmma::fragment<wmma::accumulator, 16, 16, 16, float> acc0, acc1;
            wmma::fill_fragment(acc0, 0.f);
            wmma::fill_fragment(acc1, 0.f);
#pragma unroll
            for (int ks = 0; ks < 4; ks++) {
                int k0 = ks * 16;
                wmma::fragment<wmma::matrix_a, 16, 16, 16, bf16, wmma::row_major> ah, al;
                wmma::load_matrix_sync(ah, S1h + wr * LDB + k0, LDB);
                wmma::load_matrix_sync(al, S1l + wr * LDB + k0, LDB);
                wmma::fragment<wmma::matrix_b, 16, 16, 16, bf16, wmma::row_major> bh0, bl0, bh1, bl1;
                wmma::load_matrix_sync(bh0, BufH + k0 * LDB + wc, LDB);
                wmma::load_matrix_sync(bl0, BufL + k0 * LDB + wc, LDB);
                wmma::load_matrix_sync(bh1, BufH + k0 * LDB + wc + 16, LDB);
                wmma::load_matrix_sync(bl1, BufL + k0 * LDB + wc + 16, LDB);
                wmma::mma_sync(acc0, ah, bh0, acc0);
                wmma::mma_sync(acc0, ah, bl0, acc0);
                wmma::mma_sync(acc0, al, bh0, acc0);
                wmma::mma_sync(acc1, ah, bh1, acc1);
                wmma::mma_sync(acc1, ah, bl1, acc1);
                wmma::mma_sync(acc1, al, bh1, acc1);
            }
            __syncthreads();
            wmma::store_matrix_sync(stage + wr * LDB + wc, acc0, LDB, wmma::mem_row_major);
            wmma::store_matrix_sync(stage + wr * LDB + wc + 16, acc1, LDB, wmma::mem_row_major);
        }
        __syncthreads();
        // epilogue pass2: write c*bvec
        {
            int lcb = (tid & 3) << 2;
            int r = cBase + lr;
            float* orow = ob + (size_t)r * (4 * HH);
#pragma unroll
            for (int i = 0; i < 4; i++) {
                int col = lcb + i * 16;
                float4 bv4 = *(const float4*)(stage + lr * LDB + col);
                float4 cv = *(const float4*)(cb + r * HH + hc + col);
                float4 cbv = make_float4(cv.x * bv4.x, cv.y * bv4.y, cv.z * bv4.z, cv.w * bv4.w);
                *(float4*)(orow + 3 * HH + hc + col) = cbv;
            }
        }
    }
}

extern "C" void kernel_launch(void* const* d_in, const int* in_sizes, int n_in,
                              void* d_out, int out_size) {
    (void)in_sizes; (void)n_in; (void)out_size;
    const float* c      = (const float*)d_in[0];
    const float* q      = (const float*)d_in[1];
    const int*   c_mask = (const int*)d_in[2];
    const int*   q_mask = (const int*)d_in[3];
    const float* W      = (const float*)d_in[4];
    const float* bias   = (const float*)d_in[5];
    float* out = (float*)d_out;

    bq_kernel    <<<128, 256>>>(q, bias);
    qsplit_kernel<<<768, 256>>>(q);
    qp_gemm      <<<dim3(12, 16), 256>>>(q, W);
    s_gemm       <<<dim3(8, 16), 256>>>(c, q_mask);
    colexp_kernel<<<dim3(16, 4), 256>>>(c_mask);
    t_gemm       <<<dim3(12, 16), 256>>>(c);
    final_kernel <<<dim3(8, 16, 6), 256>>>(c, out);
}

// round 13
// speedup vs baseline: 1.0522x; 1.0522x over previous
#include <cuda_runtime.h>
#include <cuda_bf16.h>
#include <mma.h>
#include <float.h>

using namespace nvcuda;

#define BB 16
#define CL 512
#define QL 64
#define HH 768
#define NEG_INF (-1e30f)
#define LDB 80   // bf16 smem row stride
#define LDF 72   // fp32 stage row stride

typedef __nv_bfloat16 bf16;

// ---------------- scratch ----------------
__device__ __align__(16) float g_bq[BB * QL];         // q . b
__device__ __align__(16) float g_s [BB * CL * QL];    // raw logits
__device__ __align__(16) float g_cinv[BB * QL];       // (unused placeholder)
__device__ __align__(16) bf16  g_ch[BB * CL * HH];    // c hi
__device__ __align__(16) bf16  g_cl[BB * CL * HH];    // c lo
__device__ __align__(16) bf16  g_qh[BB * QL * HH];    // q hi
__device__ __align__(16) bf16  g_ql[BB * QL * HH];    // q lo
__device__ __align__(16) bf16  g_qph[BB * QL * HH];   // qp hi
__device__ __align__(16) bf16  g_qpl[BB * QL * HH];   // qp lo
__device__ __align__(16) bf16  g_s1h[BB * CL * QL];   // s1 hi
__device__ __align__(16) bf16  g_s1l[BB * CL * QL];   // s1 lo
__device__ __align__(16) bf16  g_s2h[BB * CL * QL];   // s2 normalized hi
__device__ __align__(16) bf16  g_s2l[BB * CL * QL];   // s2 normalized lo
__device__ __align__(16) bf16  g_th[BB * QL * HH];    // t hi
__device__ __align__(16) bf16  g_tl[BB * QL * HH];    // t lo

__device__ __forceinline__ void split_bf16(float x, bf16& h, bf16& l) {
    h = __float2bfloat16_rn(x);
    l = __float2bfloat16_rn(x - __bfloat162float(h));
}
__device__ __forceinline__ void split_store4(bf16* ph, bf16* pl, float4 v) {
    bf16 h0, l0, h1, l1, h2, l2, h3, l3;
    split_bf16(v.x, h0, l0); split_bf16(v.y, h1, l1);
    split_bf16(v.z, h2, l2); split_bf16(v.w, h3, l3);
    *(__nv_bfloat162*)(ph)     = __nv_bfloat162(h0, h1);
    *(__nv_bfloat162*)(ph + 2) = __nv_bfloat162(h2, h3);
    *(__nv_bfloat162*)(pl)     = __nv_bfloat162(l0, l1);
    *(__nv_bfloat162*)(pl + 2) = __nv_bfloat162(l2, l3);
}

// ---------------- bq[row] = q[row,:] . b ----------------
__global__ void bq_kernel(const float* __restrict__ q, const float* __restrict__ bias) {
    int row  = blockIdx.x * 8 + (threadIdx.x >> 5);
    int lane = threadIdx.x & 31;
    const float* qr = q + row * HH;
    float s = 0.f;
    for (int d = lane; d < HH; d += 32) s += qr[d] * bias[d];
#pragma unroll
    for (int o = 16; o; o >>= 1) s += __shfl_down_sync(0xffffffffu, s, o);
    if (lane == 0) g_bq[row] = s;
}

// ---------------- q / c -> bf16 hi/lo splits ----------------
__global__ void qsplit_kernel(const float* __restrict__ q) {
    int idx = (blockIdx.x * 256 + threadIdx.x) * 4;
    float4 v = *(const float4*)(q + idx);
    split_store4(g_qh + idx, g_ql + idx, v);
}
__global__ void csplit_kernel(const float* __restrict__ c) {
    int idx = (blockIdx.x * 256 + threadIdx.x) * 4;
    float4 v = *(const float4*)(c + idx);
    split_store4(g_ch + idx, g_cl + idx, v);
}

// ---------------- qp = q @ W  (fp32 FFMA; epilogue splits to bf16) ----------------
__global__ void qp_gemm(const float* __restrict__ q, const float* __restrict__ W) {
    __shared__ __align__(16) float As[2][16][68];
    __shared__ __align__(16) float Bs[2][16][68];
    int tid = threadIdx.x;
    int tx = tid & 15, ty = tid >> 4;
    int tx4 = tx << 2, ty4 = ty << 2;
    int mBase = blockIdx.y * 64, nBase = blockIdx.x * 64;
    int lm = tid >> 2, lk = (tid & 3) << 2;
    int bk = tid >> 4, bn4 = (tid & 15) << 2;
    float acc[4][4] = {};

    float4 av = *(const float4*)(q + (mBase + lm) * HH + lk);
    float4 bv = *(const float4*)(W + bk * HH + nBase + bn4);
    As[0][lk + 0][lm] = av.x; As[0][lk + 1][lm] = av.y;
    As[0][lk + 2][lm] = av.z; As[0][lk + 3][lm] = av.w;
    *(float4*)&Bs[0][bk][bn4] = bv;
    __syncthreads();
    int buf = 0;
    for (int kt = 0; kt < HH; kt += 16) {
        bool more = (kt + 16) < HH;
        float4 nav, nbv;
        if (more) {
            nav = *(const float4*)(q + (mBase + lm) * HH + kt + 16 + lk);
            nbv = *(const float4*)(W + (kt + 16 + bk) * HH + nBase + bn4);
        }
#pragma unroll
        for (int k = 0; k < 16; k++) {
            float4 ar = *(const float4*)&As[buf][k][ty4];
            float4 br = *(const float4*)&Bs[buf][k][tx4];
            acc[0][0] = fmaf(ar.x, br.x, acc[0][0]); acc[0][1] = fmaf(ar.x, br.y, acc[0][1]);
            acc[0][2] = fmaf(ar.x, br.z, acc[0][2]); acc[0][3] = fmaf(ar.x, br.w, acc[0][3]);
            acc[1][0] = fmaf(ar.y, br.x, acc[1][0]); acc[1][1] = fmaf(ar.y, br.y, acc[1][1]);
            acc[1][2] = fmaf(ar.y, br.z, acc[1][2]); acc[1][3] = fmaf(ar.y, br.w, acc[1][3]);
            acc[2][0] = fmaf(ar.z, br.x, acc[2][0]); acc[2][1] = fmaf(ar.z, br.y, acc[2][1]);
            acc[2][2] = fmaf(ar.z, br.z, acc[2][2]); acc[2][3] = fmaf(ar.z, br.w, acc[2][3]);
            acc[3][0] = fmaf(ar.w, br.x, acc[3][0]); acc[3][1] = fmaf(ar.w, br.y, acc[3][1]);
            acc[3][2] = fmaf(ar.w, br.z, acc[3][2]); acc[3][3] = fmaf(ar.w, br.w, acc[3][3]);
        }
        if (more) {
            int nb = buf ^ 1;
            As[nb][lk + 0][lm] = nav.x; As[nb][lk + 1][lm] = nav.y;
            As[nb][lk + 2][lm] = nav.z; As[nb][lk + 3][lm] = nav.w;
            *(float4*)&Bs[nb][bk][bn4] = nbv;
            __syncthreads();
            buf = nb;
        }
    }
#pragma unroll
    for (int i = 0; i < 4; i++) {
        int idx = (mBase + ty4 + i) * HH + nBase + tx4;
        split_store4(g_qph + idx, g_qpl + idx,
                     make_float4(acc[i][0], acc[i][1], acc[i][2], acc[i][3]));
    }
}

// ---------------- s_gemm (WMMA split-bf16) + fused row softmax ----------------
// s[b,c,j] = sum_h c*qp + bq. 64x64 tile, K=768 in 64-chunks. grid (8,16).
__global__ void s_gemm(const int* __restrict__ q_mask) {
    __shared__ __align__(32) char SMEM[4 * 64 * LDB * 2];   // Ah|Al|Bh|Bl, 40960 B
    bf16* Ah = (bf16*)SMEM;
    bf16* Al = Ah + 64 * LDB;
    bf16* Bh = Al + 64 * LDB;
    bf16* Bl = Bh + 64 * LDB;
    float* stage = (float*)SMEM;                            // aliased, 64*LDF floats

    int tid = threadIdx.x;
    int b = blockIdx.y;
    int mBase = blockIdx.x * 64;
    int lr  = tid >> 2;
    int lc8 = (tid & 3) << 4;
    int wid = tid >> 5;
    int wr = (wid & 3) * 16, wc = (wid >> 2) * 32;

    wmma::fragment<wmma::accumulator, 16, 16, 16, float> acc0, acc1;
    wmma::fill_fragment(acc0, 0.f);
    wmma::fill_fragment(acc1, 0.f);

    for (int kt = 0; kt < HH; kt += 64) {
        __syncthreads();
        {
            const bf16* ah = g_ch + (b * CL + mBase + lr) * HH + kt + lc8;
            const bf16* al = g_cl + (b * CL + mBase + lr) * HH + kt + lc8;
            *(uint4*)(Ah + lr * LDB + lc8)     = *(const uint4*)(ah);
            *(uint4*)(Ah + lr * LDB + lc8 + 8) = *(const uint4*)(ah + 8);
            *(uint4*)(Al + lr * LDB + lc8)     = *(const uint4*)(al);
            *(uint4*)(Al + lr * LDB + lc8 + 8) = *(const uint4*)(al + 8);
            const bf16* bh = g_qph + (b * QL + lr) * HH + kt + lc8;   // [j][k]
            const bf16* bl = g_qpl + (b * QL + lr) * HH + kt + lc8;
            *(uint4*)(Bh + lr * LDB + lc8)     = *(const uint4*)(bh);
            *(uint4*)(Bh + lr * LDB + lc8 + 8) = *(const uint4*)(bh + 8);
            *(uint4*)(Bl + lr * LDB + lc8)     = *(const uint4*)(bl);
            *(uint4*)(Bl + lr * LDB + lc8 + 8) = *(const uint4*)(bl + 8);
        }
        __syncthreads();
#pragma unroll
        for (int ks = 0; ks < 4; ks++) {
            int k0 = ks * 16;
            wmma::fragment<wmma::matrix_a, 16, 16, 16, bf16, wmma::row_major> ah, al;
            wmma::load_matrix_sync(ah, Ah + wr * LDB + k0, LDB);
            wmma::load_matrix_sync(al, Al + wr * LDB + k0, LDB);
            // B[k][j] = qp[j][k] -> col_major over smem [j][k]
            wmma::fragment<wmma::matrix_b, 16, 16, 16, bf16, wmma::col_major> bh0, bl0, bh1, bl1;
            wmma::load_matrix_sync(bh0, Bh + wc * LDB + k0, LDB);
            wmma::load_matrix_sync(bl0, Bl + wc * LDB + k0, LDB);
            wmma::load_matrix_sync(bh1, Bh + (wc + 16) * LDB + k0, LDB);
            wmma::load_matrix_sync(bl1, Bl + (wc + 16) * LDB + k0, LDB);
            wmma::mma_sync(acc0, ah, bh0, acc0);
            wmma::mma_sync(acc0, ah, bl0, acc0);
            wmma::mma_sync(acc0, al, bh0, acc0);
            wmma::mma_sync(acc1, ah, bh1, acc1);
            wmma::mma_sync(acc1, ah, bl1, acc1);
            wmma::mma_sync(acc1, al, bh1, acc1);
        }
    }
    __syncthreads();
    wmma::store_matrix_sync(stage + wr * LDF + wc, acc0, LDF, wmma::mem_row_major);
    wmma::store_matrix_sync(stage + wr * LDF + wc + 16, acc1, LDF, wmma::mem_row_major);
    __syncthreads();

    // epilogue: bias + raw store + masked row softmax + split write.
    // 4 consecutive threads (lanes xor 1,2) own one row of 64 cols, 16 each.
    {
        int lcb = (tid & 3) << 2;
        float v[4][4];
        float mx = NEG_INF;
#pragma unroll
        for (int i = 0; i < 4; i++) {
            int col = lcb + i * 16;
            float4 a4 = *(const float4*)(stage + lr * LDF + col);
            float4 bq4 = *(const float4*)(g_bq + b * QL + col);
            int4 qm4 = *(const int4*)(q_mask + b * QL + col);
            v[i][0] = a4.x + bq4.x; v[i][1] = a4.y + bq4.y;
            v[i][2] = a4.z + bq4.z; v[i][3] = a4.w + bq4.w;
            int row = b * CL + mBase + lr;
            *(float4*)(g_s + row * QL + col) = make_float4(v[i][0], v[i][1], v[i][2], v[i][3]);
            if (!qm4.x) v[i][0] = NEG_INF;
            if (!qm4.y) v[i][1] = NEG_INF;
            if (!qm4.z) v[i][2] = NEG_INF;
            if (!qm4.w) v[i][3] = NEG_INF;
            mx = fmaxf(mx, fmaxf(fmaxf(v[i][0], v[i][1]), fmaxf(v[i][2], v[i][3])));
        }
        mx = fmaxf(mx, __shfl_xor_sync(0xffffffffu, mx, 1));
        mx = fmaxf(mx, __shfl_xor_sync(0xffffffffu, mx, 2));
        float s = 0.f;
        float e[4][4];
#pragma unroll
        for (int i = 0; i < 4; i++)
#pragma unroll
            for (int d = 0; d < 4; d++) { e[i][d] = __expf(v[i][d] - mx); s += e[i][d]; }
        s += __shfl_xor_sync(0xffffffffu, s, 1);
        s += __shfl_xor_sync(0xffffffffu, s, 2);
        float inv = 1.f / s;
        int row = b * CL + mBase + lr;
#pragma unroll
        for (int i = 0; i < 4; i++) {
            int col = lcb + i * 16;
            split_store4(g_s1h + row * QL + col, g_s1l + row * QL + col,
                         make_float4(e[i][0] * inv, e[i][1] * inv, e[i][2] * inv, e[i][3] * inv));
        }
    }
}

// ---------------- colexp: col max/exp/sum; writes NORMALIZED split bf16 s2 ----------------
__global__ void colexp_kernel(const int* __restrict__ c_mask) {
    int b  = blockIdx.x;
    int cq = blockIdx.y;
    int tid = threadIdx.x;
    int cg = tid & 3;
    int ry = tid >> 2;                   // 0..63
    int col0 = cq * 16 + cg * 4;
    __shared__ float4 red[64][4];
    const float* sp = g_s + b * CL * QL;
    const int*   mp = c_mask + b * CL;

    float4 mx = make_float4(NEG_INF, NEG_INF, NEG_INF, NEG_INF);
    float4 vv[8];
#pragma unroll
    for (int k = 0; k < 8; k++) {
        int r = ry + k * 64;
        float4 v = *(const float4*)(sp + r * QL + col0);
        if (!mp[r]) v = make_float4(NEG_INF, NEG_INF, NEG_INF, NEG_INF);
        vv[k] = v;
        mx.x = fmaxf(mx.x, v.x); mx.y = fmaxf(mx.y, v.y);
        mx.z = fmaxf(mx.z, v.z); mx.w = fmaxf(mx.w, v.w);
    }
    red[ry][cg] = mx;
    __syncthreads();
#pragma unroll
    for (int st = 32; st >= 1; st >>= 1) {
        if (ry < st) {
            float4 a = red[ry][cg], c2 = red[ry + st][cg];
            a.x = fmaxf(a.x, c2.x); a.y = fmaxf(a.y, c2.y);
            a.z = fmaxf(a.z, c2.z); a.w = fmaxf(a.w, c2.w);
            red[ry][cg] = a;
        }
        __syncthreads();
    }
    float4 cmax = red[0][cg];
    __syncthreads();

    float4 sm = make_float4(0.f, 0.f, 0.f, 0.f);
    float4 ee[8];
#pragma unroll
    for (int k = 0; k < 8; k++) {
        float4 e;
        e.x = __expf(vv[k].x - cmax.x); e.y = __expf(vv[k].y - cmax.y);
        e.z = __expf(vv[k].z - cmax.z); e.w = __expf(vv[k].w - cmax.w);
        ee[k] = e;
        sm.x += e.x; sm.y += e.y; sm.z += e.z; sm.w += e.w;
    }
    red[ry][cg] = sm;
    __syncthreads();
#pragma unroll
    for (int st = 32; st >= 1; st >>= 1) {
        if (ry < st) {
            float4 a = red[ry][cg], c2 = red[ry + st][cg];
            a.x += c2.x; a.y += c2.y; a.z += c2.z; a.w += c2.w;
            red[ry][cg] = a;
        }
        __syncthreads();
    }
    float4 ssum = red[0][cg];
    float4 inv = make_float4(1.f / ssum.x, 1.f / ssum.y, 1.f / ssum.z, 1.f / ssum.w);
#pragma unroll
    for (int k = 0; k < 8; k++) {
        int r = ry + k * 64;
        int idx = (b * CL + r) * QL + col0;
        split_store4(g_s2h + idx, g_s2l + idx,
                     make_float4(ee[k].x * inv.x, ee[k].y * inv.y,
                                 ee[k].z * inv.z, ee[k].w * inv.w));
    }
}

// ---------------- t_gemm (WMMA split-bf16): t[j,h] = sum_c s2n[c,j]*c[c,h] ----------------
// grid (12, 16). A = s2n [c][j] col-major frag; B = c split [c][h] row-major.
__global__ void t_gemm() {
    __shared__ __align__(32) char SMEM[4 * 64 * LDB * 2];
    bf16* Ah = (bf16*)SMEM;
    bf16* Al = Ah + 64 * LDB;
    bf16* Bh = Al + 64 * LDB;
    bf16* Bl = Bh + 64 * LDB;
    float* stage = (float*)SMEM;

    int tid = threadIdx.x;
    int b = blockIdx.y;
    int nBase = blockIdx.x * 64;
    int lr  = tid >> 2;
    int lc8 = (tid & 3) << 4;
    int wid = tid >> 5;
    int wr = (wid & 3) * 16, wc = (wid >> 2) * 32;

    wmma::fragment<wmma::accumulator, 16, 16, 16, float> acc0, acc1;
    wmma::fill_fragment(acc0, 0.f);
    wmma::fill_fragment(acc1, 0.f);

    for (int kt = 0; kt < CL; kt += 64) {
        __syncthreads();
        {
            // A: s2n tile [c = kt+lr][j = 0..63]
            const bf16* ah = g_s2h + (b * CL + kt + lr) * QL + lc8;
            const bf16* al = g_s2l + (b * CL + kt + lr) * QL + lc8;
            *(uint4*)(Ah + lr * LDB + lc8)     = *(const uint4*)(ah);
            *(uint4*)(Ah + lr * LDB + lc8 + 8) = *(const uint4*)(ah + 8);
            *(uint4*)(Al + lr * LDB + lc8)     = *(const uint4*)(al);
            *(uint4*)(Al + lr * LDB + lc8 + 8) = *(const uint4*)(al + 8);
            // B: c tile [c = kt+lr][h = nBase..+63]
            const bf16* bh = g_ch + (b * CL + kt + lr) * HH + nBase + lc8;
            const bf16* bl = g_cl + (b * CL + kt + lr) * HH + nBase + lc8;
            *(uint4*)(Bh + lr * LDB + lc8)     = *(const uint4*)(bh);
            *(uint4*)(Bh + lr * LDB + lc8 + 8) = *(const uint4*)(bh + 8);
            *(uint4*)(Bl + lr * LDB + lc8)     = *(const uint4*)(bl);
            *(uint4*)(Bl + lr * LDB + lc8 + 8) = *(const uint4*)(bl + 8);
        }
        __syncthreads();
#pragma unroll
        for (int ks = 0; ks < 4; ks++) {
            int k0 = ks * 16;
            // A(m=j, k=c) stored [c][j] -> col_major, ptr = Ah + k0*LDB + wr
            wmma::fragment<wmma::matrix_a, 16, 16, 16, bf16, wmma::col_major> ah, al;
            wmma::load_matrix_sync(ah, Ah + k0 * LDB + wr, LDB);
            wmma::load_matrix_sync(al, Al + k0 * LDB + wr, LDB);
            wmma::fragment<wmma::matrix_b, 16, 16, 16, bf16, wmma::row_major> bh0, bl0, bh1, bl1;
            wmma::load_matrix_sync(bh0, Bh + k0 * LDB + wc, LDB);
            wmma::load_matrix_sync(bl0, Bl + k0 * LDB + wc, LDB);
            wmma::load_matrix_sync(bh1, Bh + k0 * LDB + wc + 16, LDB);
            wmma::load_matrix_sync(bl1, Bl + k0 * LDB + wc + 16, LDB);
            wmma::mma_sync(acc0, ah, bh0, acc0);
            wmma::mma_sync(acc0, ah, bl0, acc0);
            wmma::mma_sync(acc0, al, bh0, acc0);
            wmma::mma_sync(acc1, ah, bh1, acc1);
            wmma::mma_sync(acc1, ah, bl1, acc1);
            wmma::mma_sync(acc1, al, bh1, acc1);
        }
    }
    __syncthreads();
    wmma::store_matrix_sync(stage + wr * LDF + wc, acc0, LDF, wmma::mem_row_major);
    wmma::store_matrix_sync(stage + wr * LDF + wc + 16, acc1, LDF, wmma::mem_row_major);
    __syncthreads();
    {
        int lcb = (tid & 3) << 2;
#pragma unroll
        for (int i = 0; i < 4; i++) {
            int col = lcb + i * 16;
            float4 t4 = *(const float4*)(stage + lr * LDF + col);
            int idx = (b * QL + lr) * HH + nBase + col;
            split_store4(g_th + idx, g_tl + idx, t4);
        }
    }
}

// ---------------- final: WMMA split-bf16. a = s1@q, bvec = s1@t ----------------
__global__ void final_kernel(const float* __restrict__ c, float* __restrict__ out) {
    __shared__ __align__(32) bf16 S1h[64 * LDB];
    __shared__ __align__(32) bf16 S1l[64 * LDB];
    __shared__ __align__(32) bf16 Buf2[2 * 64 * LDB];
    bf16* BufH = Buf2;
    bf16* BufL = Buf2 + 64 * LDB;
    float* stage = (float*)Buf2;

    int tid = threadIdx.x;
    int b = blockIdx.y;
    int cBase = blockIdx.x * 64;
    int hStart = blockIdx.z * 128;

    int lr  = tid >> 2;
    int lc8 = (tid & 3) << 4;

    {
        const bf16* sh = g_s1h + (b * CL + cBase + lr) * QL + lc8;
        const bf16* sl = g_s1l + (b * CL + cBase + lr) * QL + lc8;
        *(uint4*)(S1h + lr * LDB + lc8)     = *(const uint4*)(sh);
        *(uint4*)(S1h + lr * LDB + lc8 + 8) = *(const uint4*)(sh + 8);
        *(uint4*)(S1l + lr * LDB + lc8)     = *(const uint4*)(sl);
        *(uint4*)(S1l + lr * LDB + lc8 + 8) = *(const uint4*)(sl + 8);
    }

    int wid = tid >> 5;
    int wr = (wid & 3) * 16;
    int wc = (wid >> 2) * 32;

    const float* cb = c + b * CL * HH;
    float* ob = out + (size_t)(b * CL) * (4 * HH);

    for (int hc = hStart; hc < hStart + 128; hc += 64) {
        // ---- pass 1: a = s1 @ q ----
        __syncthreads();
        {
            const bf16* qh = g_qh + (b * QL + lr) * HH + hc + lc8;
            const bf16* ql = g_ql + (b * QL + lr) * HH + hc + lc8;
            *(uint4*)(BufH + lr * LDB + lc8)     = *(const uint4*)(qh);
            *(uint4*)(BufH + lr * LDB + lc8 + 8) = *(const uint4*)(qh + 8);
            *(uint4*)(BufL + lr * LDB + lc8)     = *(const uint4*)(ql);
            *(uint4*)(BufL + lr * LDB + lc8 + 8) = *(const uint4*)(ql + 8);
        }
        __syncthreads();
        {
            wmma::fragment<wmma::accumulator, 16, 16, 16, float> acc0, acc1;
            wmma::fill_fragment(acc0, 0.f);
            wmma::fill_fragment(acc1, 0.f);
#pragma unroll
            for (int ks = 0; ks < 4; ks++) {
                int k0 = ks * 16;
                wmma::fragment<wmma::matrix_a, 16, 16, 16, bf16, wmma::row_major> ah, al;
                wmma::load_matrix_sync(ah, S1h + wr * LDB + k0, LDB);
                wmma::load_matrix_sync(al, S1l + wr * LDB + k0, LDB);
                wmma::fragment<wmma::matrix_b, 16, 16, 16, bf16, wmma::row_major> bh0, bl0, bh1, bl1;
                wmma::load_matrix_sync(bh0, BufH + k0 * LDB + wc, LDB);
                wmma::load_matrix_sync(bl0, BufL + k0 * LDB + wc, LDB);
                wmma::load_matrix_sync(bh1, BufH + k0 * LDB + wc + 16, LDB);
                wmma::load_matrix_sync(bl1, BufL + k0 * LDB + wc + 16, LDB);
                wmma::mma_sync(acc0, ah, bh0, acc0);
                wmma::mma_sync(acc0, ah, bl0, acc0);
                wmma::mma_sync(acc0, al, bh0, acc0);
                wmma::mma_sync(acc1, ah, bh1, acc1);
                wmma::mma_sync(acc1, ah, bl1, acc1);
                wmma::mma_sync(acc1, al, bh1, acc1);
            }
            __syncthreads();
            wmma::store_matrix_sync(stage + wr * LDB + wc, acc0, LDB, wmma::mem_row_major);
            wmma::store_matrix_sync(stage + wr * LDB + wc + 16, acc1, LDB, wmma::mem_row_major);
        }
        __syncthreads();
        {
            int lcb = (tid & 3) << 2;
            int r = cBase + lr;
            float* orow = ob + (size_t)r * (4 * HH);
#pragma unroll
            for (int i = 0; i < 4; i++) {
                int col = lcb + i * 16;
                float4 a4 = *(const float4*)(stage + lr * LDB + col);
                float4 cv = *(const float4*)(cb + r * HH + hc + col);
                float4 ca = make_float4(cv.x * a4.x, cv.y * a4.y, cv.z * a4.z, cv.w * a4.w);
                *(float4*)(orow + 0 * HH + hc + col) = cv;
                *(float4*)(orow + 1 * HH + hc + col) = a4;
                *(float4*)(orow + 2 * HH + hc + col) = ca;
            }
        }
        // ---- pass 2: bvec = s1 @ t ----
        __syncthreads();
        {
            const bf16* th = g_th + (b * QL + lr) * HH + hc + lc8;
            const bf16* tl = g_tl + (b * QL + lr) * HH + hc + lc8;
            *(uint4*)(BufH + lr * LDB + lc8)     = *(const uint4*)(th);
            *(uint4*)(BufH + lr * LDB + lc8 + 8) = *(const uint4*)(th + 8);
            *(uint4*)(BufL + lr * LDB + lc8)     = *(const uint4*)(tl);
            *(uint4*)(BufL + lr * LDB + lc8 + 8) = *(const uint4*)(tl + 8);
        }
        __syncthreads();
        {
            wmma::fragment<wmma::accumulator, 16, 16, 16, float> acc0, acc1;
            wmma::fill_fragment(acc0, 0.f);
            wmma::fill_fragment(acc1, 0.f);
#pragma unroll
            for (int ks = 0; ks < 4; ks++) {
                int k0 = ks * 16;
                wmma::fragment<wmma::matrix_a, 16, 16, 16, bf16, wmma::row_major> ah, al;
                wmma::load_matrix_sync(ah, S1h + wr * LDB + k0, LDB);
                wmma::load_matrix_sync(al, S1l + wr * LDB + k0, LDB);
                wmma::fragment<wmma::matrix_b, 16, 16, 16, bf16, wmma::row_major> bh0, bl0, bh1, bl1;
                wmma::load_matrix_sync(bh0, BufH + k0 * LDB + wc, LDB);
                wmma::load_matrix_sync(bl0, BufL + k0 * LDB + wc, LDB);
                wmma::load_matrix_sync(bh1, BufH + k0 * LDB + wc + 16, LDB);
                wmma::load_matrix_sync(bl1, BufL + k0 * LDB + wc + 16, LDB);
                wmma::mma_sync(acc0, ah, bh0, acc0);
                wmma::mma_sync(acc0, ah, bl0, acc0);
                wmma::mma_sync(acc0, al, bh0, acc0);
                wmma::mma_sync(acc1, ah, bh1, acc1);
                wmma::mma_sync(acc1, ah, bl1, acc1);
                wmma::mma_sync(acc1, al, bh1, acc1);
            }
            __syncthreads();
            wmma::store_matrix_sync(stage + wr * LDB + wc, acc0, LDB, wmma::mem_row_major);
            wmma::store_matrix_sync(stage + wr * LDB + wc + 16, acc1, LDB, wmma::mem_row_major);
        }
        __syncthreads();
        {
            int lcb = (tid & 3) << 2;
            int r = cBase + lr;
            float* orow = ob + (size_t)r * (4 * HH);
#pragma unroll
            for (int i = 0; i < 4; i++) {
                int col = lcb + i * 16;
                float4 bv4 = *(const float4*)(stage + lr * LDB + col);
                float4 cv = *(const float4*)(cb + r * HH + hc + col);
                float4 cbv = make_float4(cv.x * bv4.x, cv.y * bv4.y, cv.z * bv4.z, cv.w * bv4.w);
                *(float4*)(orow + 3 * HH + hc + col) = cbv;
            }
        }
    }
}

extern "C" void kernel_launch(void* const* d_in, const int* in_sizes, int n_in,
                              void* d_out, int out_size) {
    (void)in_sizes; (void)n_in; (void)out_size;
    const float* c      = (const float*)d_in[0];
    const float* q      = (const float*)d_in[1];
    const int*   c_mask = (const int*)d_in[2];
    const int*   q_mask = (const int*)d_in[3];
    const float* W      = (const float*)d_in[4];
    const float* bias   = (const float*)d_in[5];
    float* out = (float*)d_out;

    bq_kernel    <<<128, 256>>>(q, bias);
    qsplit_kernel<<<768, 256>>>(q);
    csplit_kernel<<<6144, 256>>>(c);
    qp_gemm      <<<dim3(12, 16), 256>>>(q, W);
    s_gemm       <<<dim3(8, 16), 256>>>(q_mask);
    colexp_kernel<<<dim3(16, 4), 256>>>(c_mask);
    t_gemm       <<<dim3(12, 16), 256>>>();
    final_kernel <<<dim3(8, 16, 6), 256>>>(c, out);
}

// round 14
// speedup vs baseline: 1.0901x; 1.0360x over previous
#include <cuda_runtime.h>
#include <cuda_bf16.h>
#include <mma.h>
#include <float.h>

using namespace nvcuda;

#define BB 16
#define CL 512
#define QL 64
#define HH 768
#define NEG_INF (-1e30f)
#define LDB 80   // bf16 smem row stride
#define LDF 72   // fp32 stage row stride

typedef __nv_bfloat16 bf16;

// ---------------- scratch ----------------
__device__ __align__(16) float g_bq[BB * QL];         // q . b
__device__ __align__(16) float g_s [BB * CL * QL];    // raw logits
__device__ __align__(16) bf16  g_ch[BB * CL * HH];    // c hi
__device__ __align__(16) bf16  g_cl[BB * CL * HH];    // c lo
__device__ __align__(16) bf16  g_qh[BB * QL * HH];    // q hi
__device__ __align__(16) bf16  g_ql[BB * QL * HH];    // q lo
__device__ __align__(16) bf16  g_Wh[HH * HH];         // W hi
__device__ __align__(16) bf16  g_Wl[HH * HH];         // W lo
__device__ __align__(16) bf16  g_qph[BB * QL * HH];   // qp hi
__device__ __align__(16) bf16  g_qpl[BB * QL * HH];   // qp lo
__device__ __align__(16) bf16  g_s1h[BB * CL * QL];   // s1 hi
__device__ __align__(16) bf16  g_s1l[BB * CL * QL];   // s1 lo
__device__ __align__(16) bf16  g_s2h[BB * CL * QL];   // s2 normalized hi
__device__ __align__(16) bf16  g_s2l[BB * CL * QL];   // s2 normalized lo
__device__ __align__(16) bf16  g_th[BB * QL * HH];    // t hi
__device__ __align__(16) bf16  g_tl[BB * QL * HH];    // t lo

__device__ __forceinline__ void split_bf16(float x, bf16& h, bf16& l) {
    h = __float2bfloat16_rn(x);
    l = __float2bfloat16_rn(x - __bfloat162float(h));
}
__device__ __forceinline__ void split_store4(bf16* ph, bf16* pl, float4 v) {
    bf16 h0, l0, h1, l1, h2, l2, h3, l3;
    split_bf16(v.x, h0, l0); split_bf16(v.y, h1, l1);
    split_bf16(v.z, h2, l2); split_bf16(v.w, h3, l3);
    *(__nv_bfloat162*)(ph)     = __nv_bfloat162(h0, h1);
    *(__nv_bfloat162*)(ph + 2) = __nv_bfloat162(h2, h3);
    *(__nv_bfloat162*)(pl)     = __nv_bfloat162(l0, l1);
    *(__nv_bfloat162*)(pl + 2) = __nv_bfloat162(l2, l3);
}

// ---------------- bq[row] = q[row,:] . b ----------------
__global__ void bq_kernel(const float* __restrict__ q, const float* __restrict__ bias) {
    int row  = blockIdx.x * 8 + (threadIdx.x >> 5);
    int lane = threadIdx.x & 31;
    const float* qr = q + row * HH;
    float s = 0.f;
    for (int d = lane; d < HH; d += 32) s += qr[d] * bias[d];
#pragma unroll
    for (int o = 16; o; o >>= 1) s += __shfl_down_sync(0xffffffffu, s, o);
    if (lane == 0) g_bq[row] = s;
}

// ---------------- splits ----------------
__global__ void qsplit_kernel(const float* __restrict__ q) {
    int idx = (blockIdx.x * 256 + threadIdx.x) * 4;
    float4 v = *(const float4*)(q + idx);
    split_store4(g_qh + idx, g_ql + idx, v);
}
__global__ void csplit_kernel(const float* __restrict__ c) {
    int idx = (blockIdx.x * 256 + threadIdx.x) * 4;
    float4 v = *(const float4*)(c + idx);
    split_store4(g_ch + idx, g_cl + idx, v);
}
__global__ void wsplit_kernel(const float* __restrict__ W) {
    int idx = (blockIdx.x * 256 + threadIdx.x) * 4;
    float4 v = *(const float4*)(W + idx);
    split_store4(g_Wh + idx, g_Wl + idx, v);
}

// ---------------- qp = q @ W  (WMMA split-bf16) ----------------
// M=1024 (y tile = batch), N=768 (x tile), K=768. Epilogue splits to g_qp{h,l}.
__global__ void qp_gemm() {
    __shared__ __align__(32) char SMEM[4 * 64 * LDB * 2];
    bf16* Ah = (bf16*)SMEM;
    bf16* Al = Ah + 64 * LDB;
    bf16* Bh = Al + 64 * LDB;
    bf16* Bl = Bh + 64 * LDB;
    float* stage = (float*)SMEM;

    int tid = threadIdx.x;
    int mBase = blockIdx.y * 64;
    int nBase = blockIdx.x * 64;
    int lr  = tid >> 2;
    int lc8 = (tid & 3) << 4;
    int wid = tid >> 5;
    int wr = (wid & 3) * 16, wc = (wid >> 2) * 32;

    wmma::fragment<wmma::accumulator, 16, 16, 16, float> acc0, acc1;
    wmma::fill_fragment(acc0, 0.f);
    wmma::fill_fragment(acc1, 0.f);

    for (int kt = 0; kt < HH; kt += 64) {
        __syncthreads();
        {
            const bf16* ah = g_qh + (mBase + lr) * HH + kt + lc8;   // q[m][k]
            const bf16* al = g_ql + (mBase + lr) * HH + kt + lc8;
            *(uint4*)(Ah + lr * LDB + lc8)     = *(const uint4*)(ah);
            *(uint4*)(Ah + lr * LDB + lc8 + 8) = *(const uint4*)(ah + 8);
            *(uint4*)(Al + lr * LDB + lc8)     = *(const uint4*)(al);
            *(uint4*)(Al + lr * LDB + lc8 + 8) = *(const uint4*)(al + 8);
            const bf16* bh = g_Wh + (kt + lr) * HH + nBase + lc8;   // W[k][n]
            const bf16* bl = g_Wl + (kt + lr) * HH + nBase + lc8;
            *(uint4*)(Bh + lr * LDB + lc8)     = *(const uint4*)(bh);
            *(uint4*)(Bh + lr * LDB + lc8 + 8) = *(const uint4*)(bh + 8);
            *(uint4*)(Bl + lr * LDB + lc8)     = *(const uint4*)(bl);
            *(uint4*)(Bl + lr * LDB + lc8 + 8) = *(const uint4*)(bl + 8);
        }
        __syncthreads();
#pragma unroll
        for (int ks = 0; ks < 4; ks++) {
            int k0 = ks * 16;
            wmma::fragment<wmma::matrix_a, 16, 16, 16, bf16, wmma::row_major> ah, al;
            wmma::load_matrix_sync(ah, Ah + wr * LDB + k0, LDB);
            wmma::load_matrix_sync(al, Al + wr * LDB + k0, LDB);
            wmma::fragment<wmma::matrix_b, 16, 16, 16, bf16, wmma::row_major> bh0, bl0, bh1, bl1;
            wmma::load_matrix_sync(bh0, Bh + k0 * LDB + wc, LDB);
            wmma::load_matrix_sync(bl0, Bl + k0 * LDB + wc, LDB);
            wmma::load_matrix_sync(bh1, Bh + k0 * LDB + wc + 16, LDB);
            wmma::load_matrix_sync(bl1, Bl + k0 * LDB + wc + 16, LDB);
            wmma::mma_sync(acc0, ah, bh0, acc0);
            wmma::mma_sync(acc0, ah, bl0, acc0);
            wmma::mma_sync(acc0, al, bh0, acc0);
            wmma::mma_sync(acc1, ah, bh1, acc1);
            wmma::mma_sync(acc1, ah, bl1, acc1);
            wmma::mma_sync(acc1, al, bh1, acc1);
        }
    }
    __syncthreads();
    wmma::store_matrix_sync(stage + wr * LDF + wc, acc0, LDF, wmma::mem_row_major);
    wmma::store_matrix_sync(stage + wr * LDF + wc + 16, acc1, LDF, wmma::mem_row_major);
    __syncthreads();
    {
        int lcb = (tid & 3) << 2;
#pragma unroll
        for (int i = 0; i < 4; i++) {
            int col = lcb + i * 16;
            float4 v4 = *(const float4*)(stage + lr * LDF + col);
            int idx = (mBase + lr) * HH + nBase + col;
            split_store4(g_qph + idx, g_qpl + idx, v4);
        }
    }
}

// ---------------- s_gemm (WMMA split-bf16) + fused row softmax ----------------
__global__ void s_gemm(const int* __restrict__ q_mask) {
    __shared__ __align__(32) char SMEM[4 * 64 * LDB * 2];
    bf16* Ah = (bf16*)SMEM;
    bf16* Al = Ah + 64 * LDB;
    bf16* Bh = Al + 64 * LDB;
    bf16* Bl = Bh + 64 * LDB;
    float* stage = (float*)SMEM;

    int tid = threadIdx.x;
    int b = blockIdx.y;
    int mBase = blockIdx.x * 64;
    int lr  = tid >> 2;
    int lc8 = (tid & 3) << 4;
    int wid = tid >> 5;
    int wr = (wid & 3) * 16, wc = (wid >> 2) * 32;

    wmma::fragment<wmma::accumulator, 16, 16, 16, float> acc0, acc1;
    wmma::fill_fragment(acc0, 0.f);
    wmma::fill_fragment(acc1, 0.f);

    for (int kt = 0; kt < HH; kt += 64) {
        __syncthreads();
        {
            const bf16* ah = g_ch + (b * CL + mBase + lr) * HH + kt + lc8;
            const bf16* al = g_cl + (b * CL + mBase + lr) * HH + kt + lc8;
            *(uint4*)(Ah + lr * LDB + lc8)     = *(const uint4*)(ah);
            *(uint4*)(Ah + lr * LDB + lc8 + 8) = *(const uint4*)(ah + 8);
            *(uint4*)(Al + lr * LDB + lc8)     = *(const uint4*)(al);
            *(uint4*)(Al + lr * LDB + lc8 + 8) = *(const uint4*)(al + 8);
            const bf16* bh = g_qph + (b * QL + lr) * HH + kt + lc8;   // [j][k]
            const bf16* bl = g_qpl + (b * QL + lr) * HH + kt + lc8;
            *(uint4*)(Bh + lr * LDB + lc8)     = *(const uint4*)(bh);
            *(uint4*)(Bh + lr * LDB + lc8 + 8) = *(const uint4*)(bh + 8);
            *(uint4*)(Bl + lr * LDB + lc8)     = *(const uint4*)(bl);
            *(uint4*)(Bl + lr * LDB + lc8 + 8) = *(const uint4*)(bl + 8);
        }
        __syncthreads();
#pragma unroll
        for (int ks = 0; ks < 4; ks++) {
            int k0 = ks * 16;
            wmma::fragment<wmma::matrix_a, 16, 16, 16, bf16, wmma::row_major> ah, al;
            wmma::load_matrix_sync(ah, Ah + wr * LDB + k0, LDB);
            wmma::load_matrix_sync(al, Al + wr * LDB + k0, LDB);
            wmma::fragment<wmma::matrix_b, 16, 16, 16, bf16, wmma::col_major> bh0, bl0, bh1, bl1;
            wmma::load_matrix_sync(bh0, Bh + wc * LDB + k0, LDB);
            wmma::load_matrix_sync(bl0, Bl + wc * LDB + k0, LDB);
            wmma::load_matrix_sync(bh1, Bh + (wc + 16) * LDB + k0, LDB);
            wmma::load_matrix_sync(bl1, Bl + (wc + 16) * LDB + k0, LDB);
            wmma::mma_sync(acc0, ah, bh0, acc0);
            wmma::mma_sync(acc0, ah, bl0, acc0);
            wmma::mma_sync(acc0, al, bh0, acc0);
            wmma::mma_sync(acc1, ah, bh1, acc1);
            wmma::mma_sync(acc1, ah, bl1, acc1);
            wmma::mma_sync(acc1, al, bh1, acc1);
        }
    }
    __syncthreads();
    wmma::store_matrix_sync(stage + wr * LDF + wc, acc0, LDF, wmma::mem_row_major);
    wmma::store_matrix_sync(stage + wr * LDF + wc + 16, acc1, LDF, wmma::mem_row_major);
    __syncthreads();

    {
        int lcb = (tid & 3) << 2;
        float v[4][4];
        float mx = NEG_INF;
#pragma unroll
        for (int i = 0; i < 4; i++) {
            int col = lcb + i * 16;
            float4 a4 = *(const float4*)(stage + lr * LDF + col);
            float4 bq4 = *(const float4*)(g_bq + b * QL + col);
            int4 qm4 = *(const int4*)(q_mask + b * QL + col);
            v[i][0] = a4.x + bq4.x; v[i][1] = a4.y + bq4.y;
            v[i][2] = a4.z + bq4.z; v[i][3] = a4.w + bq4.w;
            int row = b * CL + mBase + lr;
            *(float4*)(g_s + row * QL + col) = make_float4(v[i][0], v[i][1], v[i][2], v[i][3]);
            if (!qm4.x) v[i][0] = NEG_INF;
            if (!qm4.y) v[i][1] = NEG_INF;
            if (!qm4.z) v[i][2] = NEG_INF;
            if (!qm4.w) v[i][3] = NEG_INF;
            mx = fmaxf(mx, fmaxf(fmaxf(v[i][0], v[i][1]), fmaxf(v[i][2], v[i][3])));
        }
        mx = fmaxf(mx, __shfl_xor_sync(0xffffffffu, mx, 1));
        mx = fmaxf(mx, __shfl_xor_sync(0xffffffffu, mx, 2));
        float s = 0.f;
        float e[4][4];
#pragma unroll
        for (int i = 0; i < 4; i++)
#pragma unroll
            for (int d = 0; d < 4; d++) { e[i][d] = __expf(v[i][d] - mx); s += e[i][d]; }
        s += __shfl_xor_sync(0xffffffffu, s, 1);
        s += __shfl_xor_sync(0xffffffffu, s, 2);
        float inv = 1.f / s;
        int row = b * CL + mBase + lr;
#pragma unroll
        for (int i = 0; i < 4; i++) {
            int col = lcb + i * 16;
            split_store4(g_s1h + row * QL + col, g_s1l + row * QL + col,
                         make_float4(e[i][0] * inv, e[i][1] * inv, e[i][2] * inv, e[i][3] * inv));
        }
    }
}

// ---------------- colexp: col max/exp/sum; writes NORMALIZED split bf16 s2 ----------------
__global__ void colexp_kernel(const int* __restrict__ c_mask) {
    int b  = blockIdx.x;
    int cq = blockIdx.y;
    int tid = threadIdx.x;
    int cg = tid & 3;
    int ry = tid >> 2;                   // 0..63
    int col0 = cq * 16 + cg * 4;
    __shared__ float4 red[64][4];
    const float* sp = g_s + b * CL * QL;
    const int*   mp = c_mask + b * CL;

    float4 mx = make_float4(NEG_INF, NEG_INF, NEG_INF, NEG_INF);
    float4 vv[8];
#pragma unroll
    for (int k = 0; k < 8; k++) {
        int r = ry + k * 64;
        float4 v = *(const float4*)(sp + r * QL + col0);
        if (!mp[r]) v = make_float4(NEG_INF, NEG_INF, NEG_INF, NEG_INF);
        vv[k] = v;
        mx.x = fmaxf(mx.x, v.x); mx.y = fmaxf(mx.y, v.y);
        mx.z = fmaxf(mx.z, v.z); mx.w = fmaxf(mx.w, v.w);
    }
    red[ry][cg] = mx;
    __syncthreads();
#pragma unroll
    for (int st = 32; st >= 1; st >>= 1) {
        if (ry < st) {
            float4 a = red[ry][cg], c2 = red[ry + st][cg];
            a.x = fmaxf(a.x, c2.x); a.y = fmaxf(a.y, c2.y);
            a.z = fmaxf(a.z, c2.z); a.w = fmaxf(a.w, c2.w);
            red[ry][cg] = a;
        }
        __syncthreads();
    }
    float4 cmax = red[0][cg];
    __syncthreads();

    float4 sm = make_float4(0.f, 0.f, 0.f, 0.f);
    float4 ee[8];
#pragma unroll
    for (int k = 0; k < 8; k++) {
        float4 e;
        e.x = __expf(vv[k].x - cmax.x); e.y = __expf(vv[k].y - cmax.y);
        e.z = __expf(vv[k].z - cmax.z); e.w = __expf(vv[k].w - cmax.w);
        ee[k] = e;
        sm.x += e.x; sm.y += e.y; sm.z += e.z; sm.w += e.w;
    }
    red[ry][cg] = sm;
    __syncthreads();
#pragma unroll
    for (int st = 32; st >= 1; st >>= 1) {
        if (ry < st) {
            float4 a = red[ry][cg], c2 = red[ry + st][cg];
            a.x += c2.x; a.y += c2.y; a.z += c2.z; a.w += c2.w;
            red[ry][cg] = a;
        }
        __syncthreads();
    }
    float4 ssum = red[0][cg];
    float4 inv = make_float4(1.f / ssum.x, 1.f / ssum.y, 1.f / ssum.z, 1.f / ssum.w);
#pragma unroll
    for (int k = 0; k < 8; k++) {
        int r = ry + k * 64;
        int idx = (b * CL + r) * QL + col0;
        split_store4(g_s2h + idx, g_s2l + idx,
                     make_float4(ee[k].x * inv.x, ee[k].y * inv.y,
                                 ee[k].z * inv.z, ee[k].w * inv.w));
    }
}

// ---------------- t_gemm (WMMA split-bf16): t[j,h] = sum_c s2n[c,j]*c[c,h] ----------------
__global__ void t_gemm() {
    __shared__ __align__(32) char SMEM[4 * 64 * LDB * 2];
    bf16* Ah = (bf16*)SMEM;
    bf16* Al = Ah + 64 * LDB;
    bf16* Bh = Al + 64 * LDB;
    bf16* Bl = Bh + 64 * LDB;
    float* stage = (float*)SMEM;

    int tid = threadIdx.x;
    int b = blockIdx.y;
    int nBase = blockIdx.x * 64;
    int lr  = tid >> 2;
    int lc8 = (tid & 3) << 4;
    int wid = tid >> 5;
    int wr = (wid & 3) * 16, wc = (wid >> 2) * 32;

    wmma::fragment<wmma::accumulator, 16, 16, 16, float> acc0, acc1;
    wmma::fill_fragment(acc0, 0.f);
    wmma::fill_fragment(acc1, 0.f);

    for (int kt = 0; kt < CL; kt += 64) {
        __syncthreads();
        {
            const bf16* ah = g_s2h + (b * CL + kt + lr) * QL + lc8;
            const bf16* al = g_s2l + (b * CL + kt + lr) * QL + lc8;
            *(uint4*)(Ah + lr * LDB + lc8)     = *(const uint4*)(ah);
            *(uint4*)(Ah + lr * LDB + lc8 + 8) = *(const uint4*)(ah + 8);
            *(uint4*)(Al + lr * LDB + lc8)     = *(const uint4*)(al);
            *(uint4*)(Al + lr * LDB + lc8 + 8) = *(const uint4*)(al + 8);
            const bf16* bh = g_ch + (b * CL + kt + lr) * HH + nBase + lc8;
            const bf16* bl = g_cl + (b * CL + kt + lr) * HH + nBase + lc8;
            *(uint4*)(Bh + lr * LDB + lc8)     = *(const uint4*)(bh);
            *(uint4*)(Bh + lr * LDB + lc8 + 8) = *(const uint4*)(bh + 8);
            *(uint4*)(Bl + lr * LDB + lc8)     = *(const uint4*)(bl);
            *(uint4*)(Bl + lr * LDB + lc8 + 8) = *(const uint4*)(bl + 8);
        }
        __syncthreads();
#pragma unroll
        for (int ks = 0; ks < 4; ks++) {
            int k0 = ks * 16;
            wmma::fragment<wmma::matrix_a, 16, 16, 16, bf16, wmma::col_major> ah, al;
            wmma::load_matrix_sync(ah, Ah + k0 * LDB + wr, LDB);
            wmma::load_matrix_sync(al, Al + k0 * LDB + wr, LDB);
            wmma::fragment<wmma::matrix_b, 16, 16, 16, bf16, wmma::row_major> bh0, bl0, bh1, bl1;
            wmma::load_matrix_sync(bh0, Bh + k0 * LDB + wc, LDB);
            wmma::load_matrix_sync(bl0, Bl + k0 * LDB + wc, LDB);
            wmma::load_matrix_sync(bh1, Bh + k0 * LDB + wc + 16, LDB);
            wmma::load_matrix_sync(bl1, Bl + k0 * LDB + wc + 16, LDB);
            wmma::mma_sync(acc0, ah, bh0, acc0);
            wmma::mma_sync(acc0, ah, bl0, acc0);
            wmma::mma_sync(acc0, al, bh0, acc0);
            wmma::mma_sync(acc1, ah, bh1, acc1);
            wmma::mma_sync(acc1, ah, bl1, acc1);
            wmma::mma_sync(acc1, al, bh1, acc1);
        }
    }
    __syncthreads();
    wmma::store_matrix_sync(stage + wr * LDF + wc, acc0, LDF, wmma::mem_row_major);
    wmma::store_matrix_sync(stage + wr * LDF + wc + 16, acc1, LDF, wmma::mem_row_major);
    __syncthreads();
    {
        int lcb = (tid & 3) << 2;
#pragma unroll
        for (int i = 0; i < 4; i++) {
            int col = lcb + i * 16;
            float4 t4 = *(const float4*)(stage + lr * LDF + col);
            int idx = (b * QL + lr) * HH + nBase + col;
            split_store4(g_th + idx, g_tl + idx, t4);
        }
    }
}

// ---------------- final: WMMA split-bf16. a = s1@q, bvec = s1@t ----------------
__global__ void final_kernel(const float* __restrict__ c, float* __restrict__ out) {
    __shared__ __align__(32) bf16 S1h[64 * LDB];
    __shared__ __align__(32) bf16 S1l[64 * LDB];
    __shared__ __align__(32) bf16 Buf2[2 * 64 * LDB];
    bf16* BufH = Buf2;
    bf16* BufL = Buf2 + 64 * LDB;
    float* stage = (float*)Buf2;

    int tid = threadIdx.x;
    int b = blockIdx.y;
    int cBase = blockIdx.x * 64;
    int hStart = blockIdx.z * 128;

    int lr  = tid >> 2;
    int lc8 = (tid & 3) << 4;

    {
        const bf16* sh = g_s1h + (b * CL + cBase + lr) * QL + lc8;
        const bf16* sl = g_s1l + (b * CL + cBase + lr) * QL + lc8;
        *(uint4*)(S1h + lr * LDB + lc8)     = *(const uint4*)(sh);
        *(uint4*)(S1h + lr * LDB + lc8 + 8) = *(const uint4*)(sh + 8);
        *(uint4*)(S1l + lr * LDB + lc8)     = *(const uint4*)(sl);
        *(uint4*)(S1l + lr * LDB + lc8 + 8) = *(const uint4*)(sl + 8);
    }

    int wid = tid >> 5;
    int wr = (wid & 3) * 16;
    int wc = (wid >> 2) * 32;

    const float* cb = c + b * CL * HH;
    float* ob = out + (size_t)(b * CL) * (4 * HH);

    for (int hc = hStart; hc < hStart + 128; hc += 64) {
        // ---- pass 1: a = s1 @ q ----
        __syncthreads();
        {
            const bf16* qh = g_qh + (b * QL + lr) * HH + hc + lc8;
            const bf16* ql = g_ql + (b * QL + lr) * HH + hc + lc8;
            *(uint4*)(BufH + lr * LDB + lc8)     = *(const uint4*)(qh);
            *(uint4*)(BufH + lr * LDB + lc8 + 8) = *(const uint4*)(qh + 8);
            *(uint4*)(BufL + lr * LDB + lc8)     = *(const uint4*)(ql);
            *(uint4*)(BufL + lr * LDB + lc8 + 8) = *(const uint4*)(ql + 8);
        }
        __syncthreads();
        {
            wmma::fragment<wmma::accumulator, 16, 16, 16, float> acc0, acc1;
            wmma::fill_fragment(acc0, 0.f);
            wmma::fill_fragment(acc1, 0.f);
#pragma unroll
            for (int ks = 0; ks < 4; ks++) {
                int k0 = ks * 16;
                wmma::fragment<wmma::matrix_a, 16, 16, 16, bf16, wmma::row_major> ah, al;
                wmma::load_matrix_sync(ah, S1h + wr * LDB + k0, LDB);
                wmma::load_matrix_sync(al, S1l + wr * LDB + k0, LDB);
                wmma::fragment<wmma::matrix_b, 16, 16, 16, bf16, wmma::row_major> bh0, bl0, bh1, bl1;
                wmma::load_matrix_sync(bh0, BufH + k0 * LDB + wc, LDB);
                wmma::load_matrix_sync(bl0, BufL + k0 * LDB + wc, LDB);
                wmma::load_matrix_sync(bh1, BufH + k0 * LDB + wc + 16, LDB);
                wmma::load_matrix_sync(bl1, BufL + k0 * LDB + wc + 16, LDB);
                wmma::mma_sync(acc0, ah, bh0, acc0);
                wmma::mma_sync(acc0, ah, bl0, acc0);
                wmma::mma_sync(acc0, al, bh0, acc0);
                wmma::mma_sync(acc1, ah, bh1, acc1);
                wmma::mma_sync(acc1, ah, bl1, acc1);
                wmma::mma_sync(acc1, al, bh1, acc1);
            }
            __syncthreads();
            wmma::store_matrix_sync(stage + wr * LDB + wc, acc0, LDB, wmma::mem_row_major);
            wmma::store_matrix_sync(stage + wr * LDB + wc + 16, acc1, LDB, wmma::mem_row_major);
        }
        __syncthreads();
        {
            int lcb = (tid & 3) << 2;
            int r = cBase + lr;
            float* orow = ob + (size_t)r * (4 * HH);
#pragma unroll
            for (int i = 0; i < 4; i++) {
                int col = lcb + i * 16;
                float4 a4 = *(const float4*)(stage + lr * LDB + col);
                float4 cv = *(const float4*)(cb + r * HH + hc + col);
                float4 ca = make_float4(cv.x * a4.x, cv.y * a4.y, cv.z * a4.z, cv.w * a4.w);
                *(float4*)(orow + 0 * HH + hc + col) = cv;
                *(float4*)(orow + 1 * HH + hc + col) = a4;
                *(float4*)(orow + 2 * HH + hc + col) = ca;
            }
        }
        // ---- pass 2: bvec = s1 @ t ----
        __syncthreads();
        {
            const bf16* th = g_th + (b * QL + lr) * HH + hc + lc8;
            const bf16* tl = g_tl + (b * QL + lr) * HH + hc + lc8;
            *(uint4*)(BufH + lr * LDB + lc8)     = *(const uint4*)(th);
            *(uint4*)(BufH + lr * LDB + lc8 + 8) = *(const uint4*)(th + 8);
            *(uint4*)(BufL + lr * LDB + lc8)     = *(const uint4*)(tl);
            *(uint4*)(BufL + lr * LDB + lc8 + 8) = *(const uint4*)(tl + 8);
        }
        __syncthreads();
        {
            wmma::fragment<wmma::accumulator, 16, 16, 16, float> acc0, acc1;
            wmma::fill_fragment(acc0, 0.f);
            wmma::fill_fragment(acc1, 0.f);
#pragma unroll
            for (int ks = 0; ks < 4; ks++) {
                int k0 = ks * 16;
                wmma::fragment<wmma::matrix_a, 16, 16, 16, bf16, wmma::row_major> ah, al;
                wmma::load_matrix_sync(ah, S1h + wr * LDB + k0, LDB);
                wmma::load_matrix_sync(al, S1l + wr * LDB + k0, LDB);
                wmma::fragment<wmma::matrix_b, 16, 16, 16, bf16, wmma::row_major> bh0, bl0, bh1, bl1;
                wmma::load_matrix_sync(bh0, BufH + k0 * LDB + wc, LDB);
                wmma::load_matrix_sync(bl0, BufL + k0 * LDB + wc, LDB);
                wmma::load_matrix_sync(bh1, BufH + k0 * LDB + wc + 16, LDB);
                wmma::load_matrix_sync(bl1, BufL + k0 * LDB + wc + 16, LDB);
                wmma::mma_sync(acc0, ah, bh0, acc0);
                wmma::mma_sync(acc0, ah, bl0, acc0);
                wmma::mma_sync(acc0, al, bh0, acc0);
                wmma::mma_sync(acc1, ah, bh1, acc1);
                wmma::mma_sync(acc1, ah, bl1, acc1);
                wmma::mma_sync(acc1, al, bh1, acc1);
            }
            __syncthreads();
            wmma::store_matrix_sync(stage + wr * LDB + wc, acc0, LDB, wmma::mem_row_major);
            wmma::store_matrix_sync(stage + wr * LDB + wc + 16, acc1, LDB, wmma::mem_row_major);
        }
        __syncthreads();
        {
            int lcb = (tid & 3) << 2;
            int r = cBase + lr;
            float* orow = ob + (size_t)r * (4 * HH);
#pragma unroll
            for (int i = 0; i < 4; i++) {
                int col = lcb + i * 16;
                float4 bv4 = *(const float4*)(stage + lr * LDB + col);
                float4 cv = *(const float4*)(cb + r * HH + hc + col);
                float4 cbv = make_float4(cv.x * bv4.x, cv.y * bv4.y, cv.z * bv4.z, cv.w * bv4.w);
                *(float4*)(orow + 3 * HH + hc + col) = cbv;
            }
        }
    }
}

extern "C" void kernel_launch(void* const* d_in, const int* in_sizes, int n_in,
                              void* d_out, int out_size) {
    (void)in_sizes; (void)n_in; (void)out_size;
    const float* c      = (const float*)d_in[0];
    const float* q      = (const float*)d_in[1];
    const int*   c_mask = (const int*)d_in[2];
    const int*   q_mask = (const int*)d_in[3];
    const float* W      = (const float*)d_in[4];
    const float* bias   = (const float*)d_in[5];
    float* out = (float*)d_out;

    bq_kernel    <<<128, 256>>>(q, bias);
    qsplit_kernel<<<768, 256>>>(q);
    csplit_kernel<<<6144, 256>>>(c);
    wsplit_kernel<<<576, 256>>>(W);
    qp_gemm      <<<dim3(12, 16), 256>>>();
    s_gemm       <<<dim3(8, 16), 256>>>(q_mask);
    colexp_kernel<<<dim3(16, 4), 256>>>(c_mask);
    t_gemm       <<<dim3(12, 16), 256>>>();
    final_kernel <<<dim3(8, 16, 6), 256>>>(c, out);
}

// round 16
// speedup vs baseline: 1.1064x; 1.0150x over previous
#include <cuda_runtime.h>
#include <cuda_bf16.h>
#include <mma.h>
#include <float.h>

using namespace nvcuda;

#define BB 16
#define CL 512
#define QL 64
#define HH 768
#define NEG_INF (-1e30f)
#define LDB 80   // bf16 smem row stride
#define LDF 72   // fp32 stage row stride

typedef __nv_bfloat16 bf16;

// ---------------- scratch ----------------
__device__ __align__(16) float g_bq[BB * QL];         // q . b
__device__ __align__(16) float g_s [BB * CL * QL];    // raw logits
__device__ __align__(16) bf16  g_ch[BB * CL * HH];    // c hi
__device__ __align__(16) bf16  g_cl[BB * CL * HH];    // c lo
__device__ __align__(16) bf16  g_qh[BB * QL * HH];    // q hi
__device__ __align__(16) bf16  g_ql[BB * QL * HH];    // q lo
__device__ __align__(16) bf16  g_Wh[HH * HH];         // W hi
__device__ __align__(16) bf16  g_Wl[HH * HH];         // W lo
__device__ __align__(16) bf16  g_qph[BB * QL * HH];   // qp hi
__device__ __align__(16) bf16  g_qpl[BB * QL * HH];   // qp lo
__device__ __align__(16) bf16  g_s1h[BB * CL * QL];   // s1 hi
__device__ __align__(16) bf16  g_s1l[BB * CL * QL];   // s1 lo
__device__ __align__(16) bf16  g_s2h[BB * CL * QL];   // s2 normalized hi
__device__ __align__(16) bf16  g_s2l[BB * CL * QL];   // s2 normalized lo
__device__ __align__(16) bf16  g_th[BB * QL * HH];    // t hi
__device__ __align__(16) bf16  g_tl[BB * QL * HH];    // t lo

__device__ __forceinline__ void split_bf16(float x, bf16& h, bf16& l) {
    h = __float2bfloat16_rn(x);
    l = __float2bfloat16_rn(x - __bfloat162float(h));
}
__device__ __forceinline__ void split_store4(bf16* ph, bf16* pl, float4 v) {
    bf16 h0, l0, h1, l1, h2, l2, h3, l3;
    split_bf16(v.x, h0, l0); split_bf16(v.y, h1, l1);
    split_bf16(v.z, h2, l2); split_bf16(v.w, h3, l3);
    *(__nv_bfloat162*)(ph)     = __nv_bfloat162(h0, h1);
    *(__nv_bfloat162*)(ph + 2) = __nv_bfloat162(h2, h3);
    *(__nv_bfloat162*)(pl)     = __nv_bfloat162(l0, l1);
    *(__nv_bfloat162*)(pl + 2) = __nv_bfloat162(l2, l3);
}

// ---------------- bq[row] = q[row,:] . b ----------------
__global__ void bq_kernel(const float* __restrict__ q, const float* __restrict__ bias) {
    int row  = blockIdx.x * 8 + (threadIdx.x >> 5);
    int lane = threadIdx.x & 31;
    const float* qr = q + row * HH;
    float s = 0.f;
    for (int d = lane; d < HH; d += 32) s += qr[d] * bias[d];
#pragma unroll
    for (int o = 16; o; o >>= 1) s += __shfl_down_sync(0xffffffffu, s, o);
    if (lane == 0) g_bq[row] = s;
}

// ---------------- merged split kernel: q | c | W ----------------
// grid = 768 + 6144 + 576 = 7488 blocks of 256 threads, 4 floats/thread.
__global__ void split_all_kernel(const float* __restrict__ q, const float* __restrict__ c,
                                 const float* __restrict__ W) {
    int blk = blockIdx.x;
    if (blk < 768) {
        int idx = (blk * 256 + threadIdx.x) * 4;
        split_store4(g_qh + idx, g_ql + idx, *(const float4*)(q + idx));
    } else if (blk < 768 + 6144) {
        int idx = ((blk - 768) * 256 + threadIdx.x) * 4;
        split_store4(g_ch + idx, g_cl + idx, *(const float4*)(c + idx));
    } else {
        int idx = ((blk - 768 - 6144) * 256 + threadIdx.x) * 4;
        split_store4(g_Wh + idx, g_Wl + idx, *(const float4*)(W + idx));
    }
}

// ==================== WMMA GEMM common shapes ====================
// 64x64 tile, 256 thr, 8 warps (4 row-groups x 2 col-groups), 3-product split.
// Double-buffered via register prefetch: 2 syncs/tile, GMEM latency behind mma.

// ---------------- qp = q @ W  (M=1024, N=768, K=768) ----------------
__global__ void qp_gemm() {
    __shared__ __align__(32) char SMEM[4 * 64 * LDB * 2];
    bf16* Ah = (bf16*)SMEM;
    bf16* Al = Ah + 64 * LDB;
    bf16* Bh = Al + 64 * LDB;
    bf16* Bl = Bh + 64 * LDB;
    float* stage = (float*)SMEM;

    int tid = threadIdx.x;
    int mBase = blockIdx.y * 64;
    int nBase = blockIdx.x * 64;
    int lr  = tid >> 2;
    int lc8 = (tid & 3) << 4;
    int wid = tid >> 5;
    int wr = (wid & 3) * 16, wc = (wid >> 2) * 32;

    const bf16* pAh = g_qh + (mBase + lr) * HH + lc8;   // + kt
    const bf16* pAl = g_ql + (mBase + lr) * HH + lc8;
    const bf16* pBh = g_Wh + lr * HH + nBase + lc8;     // + kt*HH
    const bf16* pBl = g_Wl + lr * HH + nBase + lc8;

    wmma::fragment<wmma::accumulator, 16, 16, 16, float> acc0, acc1;
    wmma::fill_fragment(acc0, 0.f);
    wmma::fill_fragment(acc1, 0.f);

    uint4 rA0 = *(const uint4*)(pAh);     uint4 rA1 = *(const uint4*)(pAh + 8);
    uint4 rA2 = *(const uint4*)(pAl);     uint4 rA3 = *(const uint4*)(pAl + 8);
    uint4 rB0 = *(const uint4*)(pBh);     uint4 rB1 = *(const uint4*)(pBh + 8);
    uint4 rB2 = *(const uint4*)(pBl);     uint4 rB3 = *(const uint4*)(pBl + 8);
    *(uint4*)(Ah + lr * LDB + lc8) = rA0; *(uint4*)(Ah + lr * LDB + lc8 + 8) = rA1;
    *(uint4*)(Al + lr * LDB + lc8) = rA2; *(uint4*)(Al + lr * LDB + lc8 + 8) = rA3;
    *(uint4*)(Bh + lr * LDB + lc8) = rB0; *(uint4*)(Bh + lr * LDB + lc8 + 8) = rB1;
    *(uint4*)(Bl + lr * LDB + lc8) = rB2; *(uint4*)(Bl + lr * LDB + lc8 + 8) = rB3;
    __syncthreads();

    for (int kt = 0; kt < HH; kt += 64) {
        bool more = (kt + 64) < HH;
        if (more) {
            rA0 = *(const uint4*)(pAh + kt + 64);           rA1 = *(const uint4*)(pAh + kt + 64 + 8);
            rA2 = *(const uint4*)(pAl + kt + 64);           rA3 = *(const uint4*)(pAl + kt + 64 + 8);
            rB0 = *(const uint4*)(pBh + (kt + 64) * HH);    rB1 = *(const uint4*)(pBh + (kt + 64) * HH + 8);
            rB2 = *(const uint4*)(pBl + (kt + 64) * HH);    rB3 = *(const uint4*)(pBl + (kt + 64) * HH + 8);
        }
#pragma unroll
        for (int ks = 0; ks < 4; ks++) {
            int k0 = ks * 16;
            wmma::fragment<wmma::matrix_a, 16, 16, 16, bf16, wmma::row_major> ah, al;
            wmma::load_matrix_sync(ah, Ah + wr * LDB + k0, LDB);
            wmma::load_matrix_sync(al, Al + wr * LDB + k0, LDB);
            wmma::fragment<wmma::matrix_b, 16, 16, 16, bf16, wmma::row_major> bh0, bl0, bh1, bl1;
            wmma::load_matrix_sync(bh0, Bh + k0 * LDB + wc, LDB);
            wmma::load_matrix_sync(bl0, Bl + k0 * LDB + wc, LDB);
            wmma::load_matrix_sync(bh1, Bh + k0 * LDB + wc + 16, LDB);
            wmma::load_matrix_sync(bl1, Bl + k0 * LDB + wc + 16, LDB);
            wmma::mma_sync(acc0, ah, bh0, acc0);
            wmma::mma_sync(acc0, ah, bl0, acc0);
            wmma::mma_sync(acc0, al, bh0, acc0);
            wmma::mma_sync(acc1, ah, bh1, acc1);
            wmma::mma_sync(acc1, ah, bl1, acc1);
            wmma::mma_sync(acc1, al, bh1, acc1);
        }
        __syncthreads();
        if (more) {
            *(uint4*)(Ah + lr * LDB + lc8) = rA0; *(uint4*)(Ah + lr * LDB + lc8 + 8) = rA1;
            *(uint4*)(Al + lr * LDB + lc8) = rA2; *(uint4*)(Al + lr * LDB + lc8 + 8) = rA3;
            *(uint4*)(Bh + lr * LDB + lc8) = rB0; *(uint4*)(Bh + lr * LDB + lc8 + 8) = rB1;
            *(uint4*)(Bl + lr * LDB + lc8) = rB2; *(uint4*)(Bl + lr * LDB + lc8 + 8) = rB3;
            __syncthreads();
        }
    }
    wmma::store_matrix_sync(stage + wr * LDF + wc, acc0, LDF, wmma::mem_row_major);
    wmma::store_matrix_sync(stage + wr * LDF + wc + 16, acc1, LDF, wmma::mem_row_major);
    __syncthreads();
    {
        int lcb = (tid & 3) << 2;
#pragma unroll
        for (int i = 0; i < 4; i++) {
            int col = lcb + i * 16;
            float4 v4 = *(const float4*)(stage + lr * LDF + col);
            int idx = (mBase + lr) * HH + nBase + col;
            split_store4(g_qph + idx, g_qpl + idx, v4);
        }
    }
}

// ---------------- s_gemm (WMMA) + fused row softmax ----------------
__global__ void s_gemm(const int* __restrict__ q_mask) {
    __shared__ __align__(32) char SMEM[4 * 64 * LDB * 2];
    bf16* Ah = (bf16*)SMEM;
    bf16* Al = Ah + 64 * LDB;
    bf16* Bh = Al + 64 * LDB;
    bf16* Bl = Bh + 64 * LDB;
    float* stage = (float*)SMEM;

    int tid = threadIdx.x;
    int b = blockIdx.y;
    int mBase = blockIdx.x * 64;
    int lr  = tid >> 2;
    int lc8 = (tid & 3) << 4;
    int wid = tid >> 5;
    int wr = (wid & 3) * 16, wc = (wid >> 2) * 32;

    const bf16* pAh = g_ch + (b * CL + mBase + lr) * HH + lc8;   // + kt
    const bf16* pAl = g_cl + (b * CL + mBase + lr) * HH + lc8;
    const bf16* pBh = g_qph + (b * QL + lr) * HH + lc8;          // + kt   [j][k]
    const bf16* pBl = g_qpl + (b * QL + lr) * HH + lc8;

    wmma::fragment<wmma::accumulator, 16, 16, 16, float> acc0, acc1;
    wmma::fill_fragment(acc0, 0.f);
    wmma::fill_fragment(acc1, 0.f);

    uint4 rA0 = *(const uint4*)(pAh);     uint4 rA1 = *(const uint4*)(pAh + 8);
    uint4 rA2 = *(const uint4*)(pAl);     uint4 rA3 = *(const uint4*)(pAl + 8);
    uint4 rB0 = *(const uint4*)(pBh);     uint4 rB1 = *(const uint4*)(pBh + 8);
    uint4 rB2 = *(const uint4*)(pBl);     uint4 rB3 = *(const uint4*)(pBl + 8);
    *(uint4*)(Ah + lr * LDB + lc8) = rA0; *(uint4*)(Ah + lr * LDB + lc8 + 8) = rA1;
    *(uint4*)(Al + lr * LDB + lc8) = rA2; *(uint4*)(Al + lr * LDB + lc8 + 8) = rA3;
    *(uint4*)(Bh + lr * LDB + lc8) = rB0; *(uint4*)(Bh + lr * LDB + lc8 + 8) = rB1;
    *(uint4*)(Bl + lr * LDB + lc8) = rB2; *(uint4*)(Bl + lr * LDB + lc8 + 8) = rB3;
    __syncthreads();

    for (int kt = 0; kt < HH; kt += 64) {
        bool more = (kt + 64) < HH;
        if (more) {
            rA0 = *(const uint4*)(pAh + kt + 64); rA1 = *(const uint4*)(pAh + kt + 64 + 8);
            rA2 = *(const uint4*)(pAl + kt + 64); rA3 = *(const uint4*)(pAl + kt + 64 + 8);
            rB0 = *(const uint4*)(pBh + kt + 64); rB1 = *(const uint4*)(pBh + kt + 64 + 8);
            rB2 = *(const uint4*)(pBl + kt + 64); rB3 = *(const uint4*)(pBl + kt + 64 + 8);
        }
#pragma unroll
        for (int ks = 0; ks < 4; ks++) {
            int k0 = ks * 16;
            wmma::fragment<wmma::matrix_a, 16, 16, 16, bf16, wmma::row_major> ah, al;
            wmma::load_matrix_sync(ah, Ah + wr * LDB + k0, LDB);
            wmma::load_matrix_sync(al, Al + wr * LDB + k0, LDB);
            wmma::fragment<wmma::matrix_b, 16, 16, 16, bf16, wmma::col_major> bh0, bl0, bh1, bl1;
            wmma::load_matrix_sync(bh0, Bh + wc * LDB + k0, LDB);
            wmma::load_matrix_sync(bl0, Bl + wc * LDB + k0, LDB);
            wmma::load_matrix_sync(bh1, Bh + (wc + 16) * LDB + k0, LDB);
            wmma::load_matrix_sync(bl1, Bl + (wc + 16) * LDB + k0, LDB);
            wmma::mma_sync(acc0, ah, bh0, acc0);
            wmma::mma_sync(acc0, ah, bl0, acc0);
            wmma::mma_sync(acc0, al, bh0, acc0);
            wmma::mma_sync(acc1, ah, bh1, acc1);
            wmma::mma_sync(acc1, ah, bl1, acc1);
            wmma::mma_sync(acc1, al, bh1, acc1);
        }
        __syncthreads();
        if (more) {
            *(uint4*)(Ah + lr * LDB + lc8) = rA0; *(uint4*)(Ah + lr * LDB + lc8 + 8) = rA1;
            *(uint4*)(Al + lr * LDB + lc8) = rA2; *(uint4*)(Al + lr * LDB + lc8 + 8) = rA3;
            *(uint4*)(Bh + lr * LDB + lc8) = rB0; *(uint4*)(Bh + lr * LDB + lc8 + 8) = rB1;
            *(uint4*)(Bl + lr * LDB + lc8) = rB2; *(uint4*)(Bl + lr * LDB + lc8 + 8) = rB3;
            __syncthreads();
        }
    }
    wmma::store_matrix_sync(stage + wr * LDF + wc, acc0, LDF, wmma::mem_row_major);
    wmma::store_matrix_sync(stage + wr * LDF + wc + 16, acc1, LDF, wmma::mem_row_major);
    __syncthreads();

    {
        int lcb = (tid & 3) << 2;
        float v[4][4];
        float mx = NEG_INF;
#pragma unroll
        for (int i = 0; i < 4; i++) {
            int col = lcb + i * 16;
            float4 a4 = *(const float4*)(stage + lr * LDF + col);
            float4 bq4 = *(const float4*)(g_bq + b * QL + col);
            int4 qm4 = *(const int4*)(q_mask + b * QL + col);
            v[i][0] = a4.x + bq4.x; v[i][1] = a4.y + bq4.y;
            v[i][2] = a4.z + bq4.z; v[i][3] = a4.w + bq4.w;
            int row = b * CL + mBase + lr;
            *(float4*)(g_s + row * QL + col) = make_float4(v[i][0], v[i][1], v[i][2], v[i][3]);
            if (!qm4.x) v[i][0] = NEG_INF;
            if (!qm4.y) v[i][1] = NEG_INF;
            if (!qm4.z) v[i][2] = NEG_INF;
            if (!qm4.w) v[i][3] = NEG_INF;
            mx = fmaxf(mx, fmaxf(fmaxf(v[i][0], v[i][1]), fmaxf(v[i][2], v[i][3])));
        }
        mx = fmaxf(mx, __shfl_xor_sync(0xffffffffu, mx, 1));
        mx = fmaxf(mx, __shfl_xor_sync(0xffffffffu, mx, 2));
        float s = 0.f;
        float e[4][4];
#pragma unroll
        for (int i = 0; i < 4; i++)
#pragma unroll
            for (int d = 0; d < 4; d++) { e[i][d] = __expf(v[i][d] - mx); s += e[i][d]; }
        s += __shfl_xor_sync(0xffffffffu, s, 1);
        s += __shfl_xor_sync(0xffffffffu, s, 2);
        float inv = 1.f / s;
        int row = b * CL + mBase + lr;
#pragma unroll
        for (int i = 0; i < 4; i++) {
            int col = lcb + i * 16;
            split_store4(g_s1h + row * QL + col, g_s1l + row * QL + col,
                         make_float4(e[i][0] * inv, e[i][1] * inv, e[i][2] * inv, e[i][3] * inv));
        }
    }
}

// ---------------- colexp ----------------
__global__ void colexp_kernel(const int* __restrict__ c_mask) {
    int b  = blockIdx.x;
    int cq = blockIdx.y;
    int tid = threadIdx.x;
    int cg = tid & 3;
    int ry = tid >> 2;                   // 0..63
    int col0 = cq * 16 + cg * 4;
    __shared__ float4 red[64][4];
    const float* sp = g_s + b * CL * QL;
    const int*   mp = c_mask + b * CL;

    float4 mx = make_float4(NEG_INF, NEG_INF, NEG_INF, NEG_INF);
    float4 vv[8];
#pragma unroll
    for (int k = 0; k < 8; k++) {
        int r = ry + k * 64;
        float4 v = *(const float4*)(sp + r * QL + col0);
        if (!mp[r]) v = make_float4(NEG_INF, NEG_INF, NEG_INF, NEG_INF);
        vv[k] = v;
        mx.x = fmaxf(mx.x, v.x); mx.y = fmaxf(mx.y, v.y);
        mx.z = fmaxf(mx.z, v.z); mx.w = fmaxf(mx.w, v.w);
    }
    red[ry][cg] = mx;
    __syncthreads();
#pragma unroll
    for (int st = 32; st >= 1; st >>= 1) {
        if (ry < st) {
            float4 a = red[ry][cg], c2 = red[ry + st][cg];
            a.x = fmaxf(a.x, c2.x); a.y = fmaxf(a.y, c2.y);
            a.z = fmaxf(a.z, c2.z); a.w = fmaxf(a.w, c2.w);
            red[ry][cg] = a;
        }
        __syncthreads();
    }
    float4 cmax = red[0][cg];
    __syncthreads();

    float4 sm = make_float4(0.f, 0.f, 0.f, 0.f);
    float4 ee[8];
#pragma unroll
    for (int k = 0; k < 8; k++) {
        float4 e;
        e.x = __expf(vv[k].x - cmax.x); e.y = __expf(vv[k].y - cmax.y);
        e.z = __expf(vv[k].z - cmax.z); e.w = __expf(vv[k].w - cmax.w);
        ee[k] = e;
        sm.x += e.x; sm.y += e.y; sm.z += e.z; sm.w += e.w;
    }
    red[ry][cg] = sm;
    __syncthreads();
#pragma unroll
    for (int st = 32; st >= 1; st >>= 1) {
        if (ry < st) {
            float4 a = red[ry][cg], c2 = red[ry + st][cg];
            a.x += c2.x; a.y += c2.y; a.z += c2.z; a.w += c2.w;
            red[ry][cg] = a;
        }
        __syncthreads();
    }
    float4 ssum = red[0][cg];
    float4 inv = make_float4(1.f / ssum.x, 1.f / ssum.y, 1.f / ssum.z, 1.f / ssum.w);
#pragma unroll
    for (int k = 0; k < 8; k++) {
        int r = ry + k * 64;
        int idx = (b * CL + r) * QL + col0;
        split_store4(g_s2h + idx, g_s2l + idx,
                     make_float4(ee[k].x * inv.x, ee[k].y * inv.y,
                                 ee[k].z * inv.z, ee[k].w * inv.w));
    }
}

// ---------------- t_gemm (WMMA): t[j,h] = sum_c s2n[c,j]*c[c,h] ----------------
__global__ void t_gemm() {
    __shared__ __align__(32) char SMEM[4 * 64 * LDB * 2];
    bf16* Ah = (bf16*)SMEM;
    bf16* Al = Ah + 64 * LDB;
    bf16* Bh = Al + 64 * LDB;
    bf16* Bl = Bh + 64 * LDB;
    float* stage = (float*)SMEM;

    int tid = threadIdx.x;
    int b = blockIdx.y;
    int nBase = blockIdx.x * 64;
    int lr  = tid >> 2;
    int lc8 = (tid & 3) << 4;
    int wid = tid >> 5;
    int wr = (wid & 3) * 16, wc = (wid >> 2) * 32;

    const bf16* pAh = g_s2h + (b * CL + lr) * QL + lc8;          // + kt*QL
    const bf16* pAl = g_s2l + (b * CL + lr) * QL + lc8;
    const bf16* pBh = g_ch + (b * CL + lr) * HH + nBase + lc8;   // + kt*HH
    const bf16* pBl = g_cl + (b * CL + lr) * HH + nBase + lc8;

    wmma::fragment<wmma::accumulator, 16, 16, 16, float> acc0, acc1;
    wmma::fill_fragment(acc0, 0.f);
    wmma::fill_fragment(acc1, 0.f);

    uint4 rA0 = *(const uint4*)(pAh);     uint4 rA1 = *(const uint4*)(pAh + 8);
    uint4 rA2 = *(const uint4*)(pAl);     uint4 rA3 = *(const uint4*)(pAl + 8);
    uint4 rB0 = *(const uint4*)(pBh);     uint4 rB1 = *(const uint4*)(pBh + 8);
    uint4 rB2 = *(const uint4*)(pBl);     uint4 rB3 = *(const uint4*)(pBl + 8);
    *(uint4*)(Ah + lr * LDB + lc8) = rA0; *(uint4*)(Ah + lr * LDB + lc8 + 8) = rA1;
    *(uint4*)(Al + lr * LDB + lc8) = rA2; *(uint4*)(Al + lr * LDB + lc8 + 8) = rA3;
    *(uint4*)(Bh + lr * LDB + lc8) = rB0; *(uint4*)(Bh + lr * LDB + lc8 + 8) = rB1;
    *(uint4*)(Bl + lr * LDB + lc8) = rB2; *(uint4*)(Bl + lr * LDB + lc8 + 8) = rB3;
    __syncthreads();

    for (int kt = 0; kt < CL; kt += 64) {
        bool more = (kt + 64) < CL;
        if (more) {
            rA0 = *(const uint4*)(pAh + (kt + 64) * QL); rA1 = *(const uint4*)(pAh + (kt + 64) * QL + 8);
            rA2 = *(const uint4*)(pAl + (kt + 64) * QL); rA3 = *(const uint4*)(pAl + (kt + 64) * QL + 8);
            rB0 = *(const uint4*)(pBh + (kt + 64) * HH); rB1 = *(const uint4*)(pBh + (kt + 64) * HH + 8);
            rB2 = *(const uint4*)(pBl + (kt + 64) * HH); rB3 = *(const uint4*)(pBl + (kt + 64) * HH + 8);
        }
#pragma unroll
        for (int ks = 0; ks < 4; ks++) {
            int k0 = ks * 16;
            wmma::fragment<wmma::matrix_a, 16, 16, 16, bf16, wmma::col_major> ah, al;
            wmma::load_matrix_sync(ah, Ah + k0 * LDB + wr, LDB);
            wmma::load_matrix_sync(al, Al + k0 * LDB + wr, LDB);
            wmma::fragment<wmma::matrix_b, 16, 16, 16, bf16, wmma::row_major> bh0, bl0, bh1, bl1;
            wmma::load_matrix_sync(bh0, Bh + k0 * LDB + wc, LDB);
            wmma::load_matrix_sync(bl0, Bl + k0 * LDB + wc, LDB);
            wmma::load_matrix_sync(bh1, Bh + k0 * LDB + wc + 16, LDB);
            wmma::load_matrix_sync(bl1, Bl + k0 * LDB + wc + 16, LDB);
            wmma::mma_sync(acc0, ah, bh0, acc0);
            wmma::mma_sync(acc0, ah, bl0, acc0);
            wmma::mma_sync(acc0, al, bh0, acc0);
            wmma::mma_sync(acc1, ah, bh1, acc1);
            wmma::mma_sync(acc1, ah, bl1, acc1);
            wmma::mma_sync(acc1, al, bh1, acc1);
        }
        __syncthreads();
        if (more) {
            *(uint4*)(Ah + lr * LDB + lc8) = rA0; *(uint4*)(Ah + lr * LDB + lc8 + 8) = rA1;
            *(uint4*)(Al + lr * LDB + lc8) = rA2; *(uint4*)(Al + lr * LDB + lc8 + 8) = rA3;
            *(uint4*)(Bh + lr * LDB + lc8) = rB0; *(uint4*)(Bh + lr * LDB + lc8 + 8) = rB1;
            *(uint4*)(Bl + lr * LDB + lc8) = rB2; *(uint4*)(Bl + lr * LDB + lc8 + 8) = rB3;
            __syncthreads();
        }
    }
    wmma::store_matrix_sync(stage + wr * LDF + wc, acc0, LDF, wmma::mem_row_major);
    wmma::store_matrix_sync(stage + wr * LDF + wc + 16, acc1, LDF, wmma::mem_row_major);
    __syncthreads();
    {
        int lcb = (tid & 3) << 2;
#pragma unroll
        for (int i = 0; i < 4; i++) {
            int col = lcb + i * 16;
            float4 t4 = *(const float4*)(stage + lr * LDF + col);
            int idx = (b * QL + lr) * HH + nBase + col;
            split_store4(g_th + idx, g_tl + idx, t4);
        }
    }
}

// ---------------- final: WMMA split-bf16. a = s1@q, bvec = s1@t ----------------
__global__ void final_kernel(const float* __restrict__ c, float* __restrict__ out) {
    __shared__ __align__(32) bf16 S1h[64 * LDB];
    __shared__ __align__(32) bf16 S1l[64 * LDB];
    __shared__ __align__(32) bf16 Buf2[2 * 64 * LDB];
    bf16* BufH = Buf2;
    bf16* BufL = Buf2 + 64 * LDB;
    float* stage = (float*)Buf2;

    int tid = threadIdx.x;
    int b = blockIdx.y;
    int cBase = blockIdx.x * 64;
    int hStart = blockIdx.z * 128;

    int lr  = tid >> 2;
    int lc8 = (tid & 3) << 4;

    {
        const bf16* sh = g_s1h + (b * CL + cBase + lr) * QL + lc8;
        const bf16* sl = g_s1l + (b * CL + cBase + lr) * QL + lc8;
        *(uint4*)(S1h + lr * LDB + lc8)     = *(const uint4*)(sh);
        *(uint4*)(S1h + lr * LDB + lc8 + 8) = *(const uint4*)(sh + 8);
        *(uint4*)(S1l + lr * LDB + lc8)     = *(const uint4*)(sl);
        *(uint4*)(S1l + lr * LDB + lc8 + 8) = *(const uint4*)(sl + 8);
    }

    int wid = tid >> 5;
    int wr = (wid & 3) * 16;
    int wc = (wid >> 2) * 32;

    const float* cb = c + b * CL * HH;
    float* ob = out + (size_t)(b * CL) * (4 * HH);
    int lcb = (tid & 3) << 2;

    for (int hc = hStart; hc < hStart + 128; hc += 64) {
        float4 cvr[4];   // cache c row chunk across both passes
#pragma unroll
        for (int i = 0; i < 4; i++)
            cvr[i] = *(const float4*)(cb + (cBase + lr) * HH + hc + lcb + i * 16);
        // ---- pass 1: a = s1 @ q ----
        __syncthreads();
        {
            const bf16* qh = g_qh + (b * QL + lr) * HH + hc + lc8;
            const bf16* ql = g_ql + (b * QL + lr) * HH + hc + lc8;
            *(uint4*)(BufH + lr * LDB + lc8)     = *(const uint4*)(qh);
            *(uint4*)(BufH + lr * LDB + lc8 + 8) = *(const uint4*)(qh + 8);
            *(uint4*)(BufL + lr * LDB + lc8)     = *(const uint4*)(ql);
            *(uint4*)(BufL + lr * LDB + lc8 + 8) = *(const uint4*)(ql + 8);
        }
        __syncthreads();
        {
            wmma::fragment<wmma::accumulator, 16, 16, 16, float> acc0, acc1;
            wmma::fill_fragment(acc0, 0.f);
            wmma::fill_fragment(acc1, 0.f);
#pragma unroll
            for (int ks = 0; ks < 4; ks++) {
                int k0 = ks * 16;
                wmma::fragment<wmma::matrix_a, 16, 16, 16, bf16, wmma::row_major> ah, al;
                wmma::load_matrix_sync(ah, S1h + wr * LDB + k0, LDB);
                wmma::load_matrix_sync(al, S1l + wr * LDB + k0, LDB);
                wmma::fragment<wmma::matrix_b, 16, 16, 16, bf16, wmma::row_major> bh0, bl0, bh1, bl1;
                wmma::load_matrix_sync(bh0, BufH + k0 * LDB + wc, LDB);
                wmma::load_matrix_sync(bl0, BufL + k0 * LDB + wc, LDB);
                wmma::load_matrix_sync(bh1, BufH + k0 * LDB + wc + 16, LDB);
                wmma::load_matrix_sync(bl1, BufL + k0 * LDB + wc + 16, LDB);
                wmma::mma_sync(acc0, ah, bh0, acc0);
                wmma::mma_sync(acc0, ah, bl0, acc0);
                wmma::mma_sync(acc0, al, bh0, acc0);
                wmma::mma_sync(acc1, ah, bh1, acc1);
                wmma::mma_sync(acc1, ah, bl1, acc1);
                wmma::mma_sync(acc1, al, bh1, acc1);
            }
            __syncthreads();
            wmma::store_matrix_sync(stage + wr * LDB + wc, acc0, LDB, wmma::mem_row_major);
            wmma::store_matrix_sync(stage + wr * LDB + wc + 16, acc1, LDB, wmma::mem_row_major);
        }
        __syncthreads();
        {
            int r = cBase + lr;
            float* orow = ob + (size_t)r * (4 * HH);
#pragma unroll
            for (int i = 0; i < 4; i++) {
                int col = lcb + i * 16;
                float4 a4 = *(const float4*)(stage + lr * LDB + col);
                float4 cv = cvr[i];
                float4 ca = make_float4(cv.x * a4.x, cv.y * a4.y, cv.z * a4.z, cv.w * a4.w);
                *(float4*)(orow + 0 * HH + hc + col) = cv;
                *(float4*)(orow + 1 * HH + hc + col) = a4;
                *(float4*)(orow + 2 * HH + hc + col) = ca;
            }
        }
        // ---- pass 2: bvec = s1 @ t ----
        __syncthreads();
        {
            const bf16* th = g_th + (b * QL + lr) * HH + hc + lc8;
            const bf16* tl = g_tl + (b * QL + lr) * HH + hc + lc8;
            *(uint4*)(BufH + lr * LDB + lc8)     = *(const uint4*)(th);
            *(uint4*)(BufH + lr * LDB + lc8 + 8) = *(const uint4*)(th + 8);
            *(uint4*)(BufL + lr * LDB + lc8)     = *(const uint4*)(tl);
            *(uint4*)(BufL + lr * LDB + lc8 + 8) = *(const uint4*)(tl + 8);
        }
        __syncthreads();
        {
            wmma::fragment<wmma::accumulator, 16, 16, 16, float> acc0, acc1;
            wmma::fill_fragment(acc0, 0.f);
            wmma::fill_fragment(acc1, 0.f);
#pragma unroll
            for (int ks = 0; ks < 4; ks++) {
                int k0 = ks * 16;
                wmma::fragment<wmma::matrix_a, 16, 16, 16, bf16, wmma::row_major> ah, al;
                wmma::load_matrix_sync(ah, S1h + wr * LDB + k0, LDB);
                wmma::load_matrix_sync(al, S1l + wr * LDB + k0, LDB);
                wmma::fragment<wmma::matrix_b, 16, 16, 16, bf16, wmma::row_major> bh0, bl0, bh1, bl1;
                wmma::load_matrix_sync(bh0, BufH + k0 * LDB + wc, LDB);
                wmma::load_matrix_sync(bl0, BufL + k0 * LDB + wc, LDB);
                wmma::load_matrix_sync(bh1, BufH + k0 * LDB + wc + 16, LDB);
                wmma::load_matrix_sync(bl1, BufL + k0 * LDB + wc + 16, LDB);
                wmma::mma_sync(acc0, ah, bh0, acc0);
                wmma::mma_sync(acc0, ah, bl0, acc0);
                wmma::mma_sync(acc0, al, bh0, acc0);
                wmma::mma_sync(acc1, ah, bh1, acc1);
                wmma::mma_sync(acc1, ah, bl1, acc1);
                wmma::mma_sync(acc1, al, bh1, acc1);
            }
            __syncthreads();
            wmma::store_matrix_sync(stage + wr * LDB + wc, acc0, LDB, wmma::mem_row_major);
            wmma::store_matrix_sync(stage + wr * LDB + wc + 16, acc1, LDB, wmma::mem_row_major);
        }
        __syncthreads();
        {
            int r = cBase + lr;
            float* orow = ob + (size_t)r * (4 * HH);
#pragma unroll
            for (int i = 0; i < 4; i++) {
                int col = lcb + i * 16;
                float4 bv4 = *(const float4*)(stage + lr * LDB + col);
                float4 cv = cvr[i];
                float4 cbv = make_float4(cv.x * bv4.x, cv.y * bv4.y, cv.z * bv4.z, cv.w * bv4.w);
                *(float4*)(orow + 3 * HH + hc + col) = cbv;
            }
        }
    }
}

extern "C" void kernel_launch(void* const* d_in, const int* in_sizes, int n_in,
                              void* d_out, int out_size) {
    (void)in_sizes; (void)n_in; (void)out_size;
    const float* c      = (const float*)d_in[0];
    const float* q      = (const float*)d_in[1];
    const int*   c_mask = (const int*)d_in[2];
    const int*   q_mask = (const int*)d_in[3];
    const float* W      = (const float*)d_in[4];
    const float* bias   = (const float*)d_in[5];
    float* out = (float*)d_out;

    bq_kernel       <<<128, 256>>>(q, bias);
    split_all_kernel<<<7488, 256>>>(q, c, W);
    qp_gemm         <<<dim3(12, 16), 256>>>();
    s_gemm          <<<dim3(8, 16), 256>>>(q_mask);
    colexp_kernel   <<<dim3(16, 4), 256>>>(c_mask);
    t_gemm          <<<dim3(12, 16), 256>>>();
    final_kernel    <<<dim3(8, 16, 6), 256>>>(c, out);
}

// round 17
// speedup vs baseline: 1.1924x; 1.0777x over previous
#include <cuda_runtime.h>
#include <cuda_bf16.h>
#include <mma.h>
#include <float.h>

using namespace nvcuda;

#define BB 16
#define CL 512
#define QL 64
#define HH 768
#define NEG_INF (-1e30f)
#define LDB 80   // bf16 smem row stride
#define LDF 72   // fp32 stage row stride (gemm kernels)
#define LDS 80   // fp32 stage row stride (final, aliases q region)

typedef __nv_bfloat16 bf16;

// ---------------- scratch ----------------
__device__ __align__(16) float g_bq[BB * QL];
__device__ __align__(16) float g_s [BB * CL * QL];
__device__ __align__(16) bf16  g_ch[BB * CL * HH];
__device__ __align__(16) bf16  g_cl[BB * CL * HH];
__device__ __align__(16) bf16  g_qh[BB * QL * HH];
__device__ __align__(16) bf16  g_ql[BB * QL * HH];
__device__ __align__(16) bf16  g_Wh[HH * HH];
__device__ __align__(16) bf16  g_Wl[HH * HH];
__device__ __align__(16) bf16  g_qph[BB * QL * HH];
__device__ __align__(16) bf16  g_qpl[BB * QL * HH];
__device__ __align__(16) bf16  g_s1h[BB * CL * QL];
__device__ __align__(16) bf16  g_s1l[BB * CL * QL];
__device__ __align__(16) bf16  g_s2h[BB * CL * QL];
__device__ __align__(16) bf16  g_s2l[BB * CL * QL];
__device__ __align__(16) bf16  g_th[BB * QL * HH];
__device__ __align__(16) bf16  g_tl[BB * QL * HH];

__device__ __forceinline__ void split_bf16(float x, bf16& h, bf16& l) {
    h = __float2bfloat16_rn(x);
    l = __float2bfloat16_rn(x - __bfloat162float(h));
}
__device__ __forceinline__ void split_store4(bf16* ph, bf16* pl, float4 v) {
    bf16 h0, l0, h1, l1, h2, l2, h3, l3;
    split_bf16(v.x, h0, l0); split_bf16(v.y, h1, l1);
    split_bf16(v.z, h2, l2); split_bf16(v.w, h3, l3);
    *(__nv_bfloat162*)(ph)     = __nv_bfloat162(h0, h1);
    *(__nv_bfloat162*)(ph + 2) = __nv_bfloat162(h2, h3);
    *(__nv_bfloat162*)(pl)     = __nv_bfloat162(l0, l1);
    *(__nv_bfloat162*)(pl + 2) = __nv_bfloat162(l2, l3);
}
__device__ __forceinline__ unsigned smem_u32(const void* p) {
    return (unsigned)__cvta_generic_to_shared(p);
}
#define CP16(dst, src) asm volatile("cp.async.cg.shared.global [%0], [%1], 16;" :: "r"(dst), "l"(src))
#define CP_COMMIT()    asm volatile("cp.async.commit_group;")
#define CP_WAIT(n)     asm volatile("cp.async.wait_group %0;" :: "n"(n))

// ---------------- bq ----------------
__global__ void bq_kernel(const float* __restrict__ q, const float* __restrict__ bias) {
    int row  = blockIdx.x * 8 + (threadIdx.x >> 5);
    int lane = threadIdx.x & 31;
    const float* qr = q + row * HH;
    float s = 0.f;
    for (int d = lane; d < HH; d += 32) s += qr[d] * bias[d];
#pragma unroll
    for (int o = 16; o; o >>= 1) s += __shfl_down_sync(0xffffffffu, s, o);
    if (lane == 0) g_bq[row] = s;
}

// ---------------- merged split: q | c | W ----------------
__global__ void split_all_kernel(const float* __restrict__ q, const float* __restrict__ c,
                                 const float* __restrict__ W) {
    int blk = blockIdx.x;
    if (blk < 768) {
        int idx = (blk * 256 + threadIdx.x) * 4;
        split_store4(g_qh + idx, g_ql + idx, *(const float4*)(q + idx));
    } else if (blk < 768 + 6144) {
        int idx = ((blk - 768) * 256 + threadIdx.x) * 4;
        split_store4(g_ch + idx, g_cl + idx, *(const float4*)(c + idx));
    } else {
        int idx = ((blk - 768 - 6144) * 256 + threadIdx.x) * 4;
        split_store4(g_Wh + idx, g_Wl + idx, *(const float4*)(W + idx));
    }
}

// ---------------- qp = q @ W (WMMA, reg-prefetch double buffer) ----------------
__global__ void qp_gemm() {
    __shared__ __align__(32) char SMEM[4 * 64 * LDB * 2];
    bf16* Ah = (bf16*)SMEM;
    bf16* Al = Ah + 64 * LDB;
    bf16* Bh = Al + 64 * LDB;
    bf16* Bl = Bh + 64 * LDB;
    float* stage = (float*)SMEM;

    int tid = threadIdx.x;
    int mBase = blockIdx.y * 64;
    int nBase = blockIdx.x * 64;
    int lr  = tid >> 2;
    int lc8 = (tid & 3) << 4;
    int wid = tid >> 5;
    int wr = (wid & 3) * 16, wc = (wid >> 2) * 32;

    const bf16* pAh = g_qh + (mBase + lr) * HH + lc8;
    const bf16* pAl = g_ql + (mBase + lr) * HH + lc8;
    const bf16* pBh = g_Wh + lr * HH + nBase + lc8;
    const bf16* pBl = g_Wl + lr * HH + nBase + lc8;

    wmma::fragment<wmma::accumulator, 16, 16, 16, float> acc0, acc1;
    wmma::fill_fragment(acc0, 0.f);
    wmma::fill_fragment(acc1, 0.f);

    uint4 rA0 = *(const uint4*)(pAh);     uint4 rA1 = *(const uint4*)(pAh + 8);
    uint4 rA2 = *(const uint4*)(pAl);     uint4 rA3 = *(const uint4*)(pAl + 8);
    uint4 rB0 = *(const uint4*)(pBh);     uint4 rB1 = *(const uint4*)(pBh + 8);
    uint4 rB2 = *(const uint4*)(pBl);     uint4 rB3 = *(const uint4*)(pBl + 8);
    *(uint4*)(Ah + lr * LDB + lc8) = rA0; *(uint4*)(Ah + lr * LDB + lc8 + 8) = rA1;
    *(uint4*)(Al + lr * LDB + lc8) = rA2; *(uint4*)(Al + lr * LDB + lc8 + 8) = rA3;
    *(uint4*)(Bh + lr * LDB + lc8) = rB0; *(uint4*)(Bh + lr * LDB + lc8 + 8) = rB1;
    *(uint4*)(Bl + lr * LDB + lc8) = rB2; *(uint4*)(Bl + lr * LDB + lc8 + 8) = rB3;
    __syncthreads();

    for (int kt = 0; kt < HH; kt += 64) {
        bool more = (kt + 64) < HH;
        if (more) {
            rA0 = *(const uint4*)(pAh + kt + 64);        rA1 = *(const uint4*)(pAh + kt + 64 + 8);
            rA2 = *(const uint4*)(pAl + kt + 64);        rA3 = *(const uint4*)(pAl + kt + 64 + 8);
            rB0 = *(const uint4*)(pBh + (kt + 64) * HH); rB1 = *(const uint4*)(pBh + (kt + 64) * HH + 8);
            rB2 = *(const uint4*)(pBl + (kt + 64) * HH); rB3 = *(const uint4*)(pBl + (kt + 64) * HH + 8);
        }
#pragma unroll
        for (int ks = 0; ks < 4; ks++) {
            int k0 = ks * 16;
            wmma::fragment<wmma::matrix_a, 16, 16, 16, bf16, wmma::row_major> ah, al;
            wmma::load_matrix_sync(ah, Ah + wr * LDB + k0, LDB);
            wmma::load_matrix_sync(al, Al + wr * LDB + k0, LDB);
            wmma::fragment<wmma::matrix_b, 16, 16, 16, bf16, wmma::row_major> bh0, bl0, bh1, bl1;
            wmma::load_matrix_sync(bh0, Bh + k0 * LDB + wc, LDB);
            wmma::load_matrix_sync(bl0, Bl + k0 * LDB + wc, LDB);
            wmma::load_matrix_sync(bh1, Bh + k0 * LDB + wc + 16, LDB);
            wmma::load_matrix_sync(bl1, Bl + k0 * LDB + wc + 16, LDB);
            wmma::mma_sync(acc0, ah, bh0, acc0);
            wmma::mma_sync(acc0, ah, bl0, acc0);
            wmma::mma_sync(acc0, al, bh0, acc0);
            wmma::mma_sync(acc1, ah, bh1, acc1);
            wmma::mma_sync(acc1, ah, bl1, acc1);
            wmma::mma_sync(acc1, al, bh1, acc1);
        }
        __syncthreads();
        if (more) {
            *(uint4*)(Ah + lr * LDB + lc8) = rA0; *(uint4*)(Ah + lr * LDB + lc8 + 8) = rA1;
            *(uint4*)(Al + lr * LDB + lc8) = rA2; *(uint4*)(Al + lr * LDB + lc8 + 8) = rA3;
            *(uint4*)(Bh + lr * LDB + lc8) = rB0; *(uint4*)(Bh + lr * LDB + lc8 + 8) = rB1;
            *(uint4*)(Bl + lr * LDB + lc8) = rB2; *(uint4*)(Bl + lr * LDB + lc8 + 8) = rB3;
            __syncthreads();
        }
    }
    wmma::store_matrix_sync(stage + wr * LDF + wc, acc0, LDF, wmma::mem_row_major);
    wmma::store_matrix_sync(stage + wr * LDF + wc + 16, acc1, LDF, wmma::mem_row_major);
    __syncthreads();
    {
        int lcb = (tid & 3) << 2;
#pragma unroll
        for (int i = 0; i < 4; i++) {
            int col = lcb + i * 16;
            float4 v4 = *(const float4*)(stage + lr * LDF + col);
            int idx = (mBase + lr) * HH + nBase + col;
            split_store4(g_qph + idx, g_qpl + idx, v4);
        }
    }
}

// ---------------- s_gemm (WMMA) + fused row softmax ----------------
__global__ void s_gemm(const int* __restrict__ q_mask) {
    __shared__ __align__(32) char SMEM[4 * 64 * LDB * 2];
    bf16* Ah = (bf16*)SMEM;
    bf16* Al = Ah + 64 * LDB;
    bf16* Bh = Al + 64 * LDB;
    bf16* Bl = Bh + 64 * LDB;
    float* stage = (float*)SMEM;

    int tid = threadIdx.x;
    int b = blockIdx.y;
    int mBase = blockIdx.x * 64;
    int lr  = tid >> 2;
    int lc8 = (tid & 3) << 4;
    int wid = tid >> 5;
    int wr = (wid & 3) * 16, wc = (wid >> 2) * 32;

    const bf16* pAh = g_ch + (b * CL + mBase + lr) * HH + lc8;
    const bf16* pAl = g_cl + (b * CL + mBase + lr) * HH + lc8;
    const bf16* pBh = g_qph + (b * QL + lr) * HH + lc8;
    const bf16* pBl = g_qpl + (b * QL + lr) * HH + lc8;

    wmma::fragment<wmma::accumulator, 16, 16, 16, float> acc0, acc1;
    wmma::fill_fragment(acc0, 0.f);
    wmma::fill_fragment(acc1, 0.f);

    uint4 rA0 = *(const uint4*)(pAh);     uint4 rA1 = *(const uint4*)(pAh + 8);
    uint4 rA2 = *(const uint4*)(pAl);     uint4 rA3 = *(const uint4*)(pAl + 8);
    uint4 rB0 = *(const uint4*)(pBh);     uint4 rB1 = *(const uint4*)(pBh + 8);
    uint4 rB2 = *(const uint4*)(pBl);     uint4 rB3 = *(const uint4*)(pBl + 8);
    *(uint4*)(Ah + lr * LDB + lc8) = rA0; *(uint4*)(Ah + lr * LDB + lc8 + 8) = rA1;
    *(uint4*)(Al + lr * LDB + lc8) = rA2; *(uint4*)(Al + lr * LDB + lc8 + 8) = rA3;
    *(uint4*)(Bh + lr * LDB + lc8) = rB0; *(uint4*)(Bh + lr * LDB + lc8 + 8) = rB1;
    *(uint4*)(Bl + lr * LDB + lc8) = rB2; *(uint4*)(Bl + lr * LDB + lc8 + 8) = rB3;
    __syncthreads();

    for (int kt = 0; kt < HH; kt += 64) {
        bool more = (kt + 64) < HH;
        if (more) {
            rA0 = *(const uint4*)(pAh + kt + 64); rA1 = *(const uint4*)(pAh + kt + 64 + 8);
            rA2 = *(const uint4*)(pAl + kt + 64); rA3 = *(const uint4*)(pAl + kt + 64 + 8);
            rB0 = *(const uint4*)(pBh + kt + 64); rB1 = *(const uint4*)(pBh + kt + 64 + 8);
            rB2 = *(const uint4*)(pBl + kt + 64); rB3 = *(const uint4*)(pBl + kt + 64 + 8);
        }
#pragma unroll
        for (int ks = 0; ks < 4; ks++) {
            int k0 = ks * 16;
            wmma::fragment<wmma::matrix_a, 16, 16, 16, bf16, wmma::row_major> ah, al;
            wmma::load_matrix_sync(ah, Ah + wr * LDB + k0, LDB);
            wmma::load_matrix_sync(al, Al + wr * LDB + k0, LDB);
            wmma::fragment<wmma::matrix_b, 16, 16, 16, bf16, wmma::col_major> bh0, bl0, bh1, bl1;
            wmma::load_matrix_sync(bh0, Bh + wc * LDB + k0, LDB);
            wmma::load_matrix_sync(bl0, Bl + wc * LDB + k0, LDB);
            wmma::load_matrix_sync(bh1, Bh + (wc + 16) * LDB + k0, LDB);
            wmma::load_matrix_sync(bl1, Bl + (wc + 16) * LDB + k0, LDB);
            wmma::mma_sync(acc0, ah, bh0, acc0);
            wmma::mma_sync(acc0, ah, bl0, acc0);
            wmma::mma_sync(acc0, al, bh0, acc0);
            wmma::mma_sync(acc1, ah, bh1, acc1);
            wmma::mma_sync(acc1, ah, bl1, acc1);
            wmma::mma_sync(acc1, al, bh1, acc1);
        }
        __syncthreads();
        if (more) {
            *(uint4*)(Ah + lr * LDB + lc8) = rA0; *(uint4*)(Ah + lr * LDB + lc8 + 8) = rA1;
            *(uint4*)(Al + lr * LDB + lc8) = rA2; *(uint4*)(Al + lr * LDB + lc8 + 8) = rA3;
            *(uint4*)(Bh + lr * LDB + lc8) = rB0; *(uint4*)(Bh + lr * LDB + lc8 + 8) = rB1;
            *(uint4*)(Bl + lr * LDB + lc8) = rB2; *(uint4*)(Bl + lr * LDB + lc8 + 8) = rB3;
            __syncthreads();
        }
    }
    wmma::store_matrix_sync(stage + wr * LDF + wc, acc0, LDF, wmma::mem_row_major);
    wmma::store_matrix_sync(stage + wr * LDF + wc + 16, acc1, LDF, wmma::mem_row_major);
    __syncthreads();

    {
        int lcb = (tid & 3) << 2;
        float v[4][4];
        float mx = NEG_INF;
#pragma unroll
        for (int i = 0; i < 4; i++) {
            int col = lcb + i * 16;
            float4 a4 = *(const float4*)(stage + lr * LDF + col);
            float4 bq4 = *(const float4*)(g_bq + b * QL + col);
            int4 qm4 = *(const int4*)(q_mask + b * QL + col);
            v[i][0] = a4.x + bq4.x; v[i][1] = a4.y + bq4.y;
            v[i][2] = a4.z + bq4.z; v[i][3] = a4.w + bq4.w;
            int row = b * CL + mBase + lr;
            *(float4*)(g_s + row * QL + col) = make_float4(v[i][0], v[i][1], v[i][2], v[i][3]);
            if (!qm4.x) v[i][0] = NEG_INF;
            if (!qm4.y) v[i][1] = NEG_INF;
            if (!qm4.z) v[i][2] = NEG_INF;
            if (!qm4.w) v[i][3] = NEG_INF;
            mx = fmaxf(mx, fmaxf(fmaxf(v[i][0], v[i][1]), fmaxf(v[i][2], v[i][3])));
        }
        mx = fmaxf(mx, __shfl_xor_sync(0xffffffffu, mx, 1));
        mx = fmaxf(mx, __shfl_xor_sync(0xffffffffu, mx, 2));
        float s = 0.f;
        float e[4][4];
#pragma unroll
        for (int i = 0; i < 4; i++)
#pragma unroll
            for (int d = 0; d < 4; d++) { e[i][d] = __expf(v[i][d] - mx); s += e[i][d]; }
        s += __shfl_xor_sync(0xffffffffu, s, 1);
        s += __shfl_xor_sync(0xffffffffu, s, 2);
        float inv = 1.f / s;
        int row = b * CL + mBase + lr;
#pragma unroll
        for (int i = 0; i < 4; i++) {
            int col = lcb + i * 16;
            split_store4(g_s1h + row * QL + col, g_s1l + row * QL + col,
                         make_float4(e[i][0] * inv, e[i][1] * inv, e[i][2] * inv, e[i][3] * inv));
        }
    }
}

// ---------------- colexp ----------------
__global__ void colexp_kernel(const int* __restrict__ c_mask) {
    int b  = blockIdx.x;
    int cq = blockIdx.y;
    int tid = threadIdx.x;
    int cg = tid & 3;
    int ry = tid >> 2;
    int col0 = cq * 16 + cg * 4;
    __shared__ float4 red[64][4];
    const float* sp = g_s + b * CL * QL;
    const int*   mp = c_mask + b * CL;

    float4 mx = make_float4(NEG_INF, NEG_INF, NEG_INF, NEG_INF);
    float4 vv[8];
#pragma unroll
    for (int k = 0; k < 8; k++) {
        int r = ry + k * 64;
        float4 v = *(const float4*)(sp + r * QL + col0);
        if (!mp[r]) v = make_float4(NEG_INF, NEG_INF, NEG_INF, NEG_INF);
        vv[k] = v;
        mx.x = fmaxf(mx.x, v.x); mx.y = fmaxf(mx.y, v.y);
        mx.z = fmaxf(mx.z, v.z); mx.w = fmaxf(mx.w, v.w);
    }
    red[ry][cg] = mx;
    __syncthreads();
#pragma unroll
    for (int st = 32; st >= 1; st >>= 1) {
        if (ry < st) {
            float4 a = red[ry][cg], c2 = red[ry + st][cg];
            a.x = fmaxf(a.x, c2.x); a.y = fmaxf(a.y, c2.y);
            a.z = fmaxf(a.z, c2.z); a.w = fmaxf(a.w, c2.w);
            red[ry][cg] = a;
        }
        __syncthreads();
    }
    float4 cmax = red[0][cg];
    __syncthreads();

    float4 sm = make_float4(0.f, 0.f, 0.f, 0.f);
    float4 ee[8];
#pragma unroll
    for (int k = 0; k < 8; k++) {
        float4 e;
        e.x = __expf(vv[k].x - cmax.x); e.y = __expf(vv[k].y - cmax.y);
        e.z = __expf(vv[k].z - cmax.z); e.w = __expf(vv[k].w - cmax.w);
        ee[k] = e;
        sm.x += e.x; sm.y += e.y; sm.z += e.z; sm.w += e.w;
    }
    red[ry][cg] = sm;
    __syncthreads();
#pragma unroll
    for (int st = 32; st >= 1; st >>= 1) {
        if (ry < st) {
            float4 a = red[ry][cg], c2 = red[ry + st][cg];
            a.x += c2.x; a.y += c2.y; a.z += c2.z; a.w += c2.w;
            red[ry][cg] = a;
        }
        __syncthreads();
    }
    float4 ssum = red[0][cg];
    float4 inv = make_float4(1.f / ssum.x, 1.f / ssum.y, 1.f / ssum.z, 1.f / ssum.w);
#pragma unroll
    for (int k = 0; k < 8; k++) {
        int r = ry + k * 64;
        int idx = (b * CL + r) * QL + col0;
        split_store4(g_s2h + idx, g_s2l + idx,
                     make_float4(ee[k].x * inv.x, ee[k].y * inv.y,
                                 ee[k].z * inv.z, ee[k].w * inv.w));
    }
}

// ---------------- t_gemm (WMMA) ----------------
__global__ void t_gemm() {
    __shared__ __align__(32) char SMEM[4 * 64 * LDB * 2];
    bf16* Ah = (bf16*)SMEM;
    bf16* Al = Ah + 64 * LDB;
    bf16* Bh = Al + 64 * LDB;
    bf16* Bl = Bh + 64 * LDB;
    float* stage = (float*)SMEM;

    int tid = threadIdx.x;
    int b = blockIdx.y;
    int nBase = blockIdx.x * 64;
    int lr  = tid >> 2;
    int lc8 = (tid & 3) << 4;
    int wid = tid >> 5;
    int wr = (wid & 3) * 16, wc = (wid >> 2) * 32;

    const bf16* pAh = g_s2h + (b * CL + lr) * QL + lc8;
    const bf16* pAl = g_s2l + (b * CL + lr) * QL + lc8;
    const bf16* pBh = g_ch + (b * CL + lr) * HH + nBase + lc8;
    const bf16* pBl = g_cl + (b * CL + lr) * HH + nBase + lc8;

    wmma::fragment<wmma::accumulator, 16, 16, 16, float> acc0, acc1;
    wmma::fill_fragment(acc0, 0.f);
    wmma::fill_fragment(acc1, 0.f);

    uint4 rA0 = *(const uint4*)(pAh);     uint4 rA1 = *(const uint4*)(pAh + 8);
    uint4 rA2 = *(const uint4*)(pAl);     uint4 rA3 = *(const uint4*)(pAl + 8);
    uint4 rB0 = *(const uint4*)(pBh);     uint4 rB1 = *(const uint4*)(pBh + 8);
    uint4 rB2 = *(const uint4*)(pBl);     uint4 rB3 = *(const uint4*)(pBl + 8);
    *(uint4*)(Ah + lr * LDB + lc8) = rA0; *(uint4*)(Ah + lr * LDB + lc8 + 8) = rA1;
    *(uint4*)(Al + lr * LDB + lc8) = rA2; *(uint4*)(Al + lr * LDB + lc8 + 8) = rA3;
    *(uint4*)(Bh + lr * LDB + lc8) = rB0; *(uint4*)(Bh + lr * LDB + lc8 + 8) = rB1;
    *(uint4*)(Bl + lr * LDB + lc8) = rB2; *(uint4*)(Bl + lr * LDB + lc8 + 8) = rB3;
    __syncthreads();

    for (int kt = 0; kt < CL; kt += 64) {
        bool more = (kt + 64) < CL;
        if (more) {
            rA0 = *(const uint4*)(pAh + (kt + 64) * QL); rA1 = *(const uint4*)(pAh + (kt + 64) * QL + 8);
            rA2 = *(const uint4*)(pAl + (kt + 64) * QL); rA3 = *(const uint4*)(pAl + (kt + 64) * QL + 8);
            rB0 = *(const uint4*)(pBh + (kt + 64) * HH); rB1 = *(const uint4*)(pBh + (kt + 64) * HH + 8);
            rB2 = *(const uint4*)(pBl + (kt + 64) * HH); rB3 = *(const uint4*)(pBl + (kt + 64) * HH + 8);
        }
#pragma unroll
        for (int ks = 0; ks < 4; ks++) {
            int k0 = ks * 16;
            wmma::fragment<wmma::matrix_a, 16, 16, 16, bf16, wmma::col_major> ah, al;
            wmma::load_matrix_sync(ah, Ah + k0 * LDB + wr, LDB);
            wmma::load_matrix_sync(al, Al + k0 * LDB + wr, LDB);
            wmma::fragment<wmma::matrix_b, 16, 16, 16, bf16, wmma::row_major> bh0, bl0, bh1, bl1;
            wmma::load_matrix_sync(bh0, Bh + k0 * LDB + wc, LDB);
            wmma::load_matrix_sync(bl0, Bl + k0 * LDB + wc, LDB);
            wmma::load_matrix_sync(bh1, Bh + k0 * LDB + wc + 16, LDB);
            wmma::load_matrix_sync(bl1, Bl + k0 * LDB + wc + 16, LDB);
            wmma::mma_sync(acc0, ah, bh0, acc0);
            wmma::mma_sync(acc0, ah, bl0, acc0);
            wmma::mma_sync(acc0, al, bh0, acc0);
            wmma::mma_sync(acc1, ah, bh1, acc1);
            wmma::mma_sync(acc1, ah, bl1, acc1);
            wmma::mma_sync(acc1, al, bh1, acc1);
        }
        __syncthreads();
        if (more) {
            *(uint4*)(Ah + lr * LDB + lc8) = rA0; *(uint4*)(Ah + lr * LDB + lc8 + 8) = rA1;
            *(uint4*)(Al + lr * LDB + lc8) = rA2; *(uint4*)(Al + lr * LDB + lc8 + 8) = rA3;
            *(uint4*)(Bh + lr * LDB + lc8) = rB0; *(uint4*)(Bh + lr * LDB + lc8 + 8) = rB1;
            *(uint4*)(Bl + lr * LDB + lc8) = rB2; *(uint4*)(Bl + lr * LDB + lc8 + 8) = rB3;
            __syncthreads();
        }
    }
    wmma::store_matrix_sync(stage + wr * LDF + wc, acc0, LDF, wmma::mem_row_major);
    wmma::store_matrix_sync(stage + wr * LDF + wc + 16, acc1, LDF, wmma::mem_row_major);
    __syncthreads();
    {
        int lcb = (tid & 3) << 2;
#pragma unroll
        for (int i = 0; i < 4; i++) {
            int col = lcb + i * 16;
            float4 t4 = *(const float4*)(stage + lr * LDF + col);
            int idx = (b * QL + lr) * HH + nBase + col;
            split_store4(g_th + idx, g_tl + idx, t4);
        }
    }
}

// ---------------- final: cp.async pipelined, one 64-col chunk per CTA ----------------
// grid (8 ctiles, 16 b, 12 z). Dynamic smem: S1(20480) | Q(20480) | T(20480).
// stage (fp32, LDS=80 stride, 20480 B) aliases the Q region after pass 1.
__global__ void final_kernel(const float* __restrict__ c, float* __restrict__ out) {
    extern __shared__ __align__(32) char DSM[];
    bf16* S1h = (bf16*)DSM;
    bf16* S1l = S1h + 64 * LDB;
    bf16* Qh  = S1l + 64 * LDB;
    bf16* Ql  = Qh  + 64 * LDB;
    bf16* Th  = Ql  + 64 * LDB;
    bf16* Tl  = Th  + 64 * LDB;
    float* stage = (float*)Qh;   // 64*LDS floats = 20480 B = Q region exactly

    int tid = threadIdx.x;
    int b = blockIdx.y;
    int cBase = blockIdx.x * 64;
    int hc = blockIdx.z * 64;

    int lr  = tid >> 2;
    int lc8 = (tid & 3) << 4;
    int lcb = (tid & 3) << 2;
    int wid = tid >> 5;
    int wr = (wid & 3) * 16;
    int wc = (wid >> 2) * 32;

    // group 0: S1 tile
    {
        const bf16* sh = g_s1h + (b * CL + cBase + lr) * QL + lc8;
        const bf16* sl = g_s1l + (b * CL + cBase + lr) * QL + lc8;
        CP16(smem_u32(S1h + lr * LDB + lc8), sh);
        CP16(smem_u32(S1h + lr * LDB + lc8 + 8), sh + 8);
        CP16(smem_u32(S1l + lr * LDB + lc8), sl);
        CP16(smem_u32(S1l + lr * LDB + lc8 + 8), sl + 8);
        CP_COMMIT();
    }
    // group 1: q chunk
    {
        const bf16* qh = g_qh + (b * QL + lr) * HH + hc + lc8;
        const bf16* ql = g_ql + (b * QL + lr) * HH + hc + lc8;
        CP16(smem_u32(Qh + lr * LDB + lc8), qh);
        CP16(smem_u32(Qh + lr * LDB + lc8 + 8), qh + 8);
        CP16(smem_u32(Ql + lr * LDB + lc8), ql);
        CP16(smem_u32(Ql + lr * LDB + lc8 + 8), ql + 8);
        CP_COMMIT();
    }
    // group 2: t chunk
    {
        const bf16* th = g_th + (b * QL + lr) * HH + hc + lc8;
        const bf16* tl = g_tl + (b * QL + lr) * HH + hc + lc8;
        CP16(smem_u32(Th + lr * LDB + lc8), th);
        CP16(smem_u32(Th + lr * LDB + lc8 + 8), th + 8);
        CP16(smem_u32(Tl + lr * LDB + lc8), tl);
        CP16(smem_u32(Tl + lr * LDB + lc8 + 8), tl + 8);
        CP_COMMIT();
    }
    // c rows (regular LDG, overlaps with everything)
    const float* cb = c + b * CL * HH;
    float4 cvr[4];
#pragma unroll
    for (int i = 0; i < 4; i++)
        cvr[i] = *(const float4*)(cb + (cBase + lr) * HH + hc + lcb + i * 16);

    float* ob = out + (size_t)(b * CL) * (4 * HH);

    CP_WAIT(1);           // S1 + Q arrived (T may still be in flight)
    __syncthreads();

    // ---- pass 1: a = s1 @ q ----
    wmma::fragment<wmma::accumulator, 16, 16, 16, float> acc0, acc1;
    wmma::fill_fragment(acc0, 0.f);
    wmma::fill_fragment(acc1, 0.f);
#pragma unroll
    for (int ks = 0; ks < 4; ks++) {
        int k0 = ks * 16;
        wmma::fragment<wmma::matrix_a, 16, 16, 16, bf16, wmma::row_major> ah, al;
        wmma::load_matrix_sync(ah, S1h + wr * LDB + k0, LDB);
        wmma::load_matrix_sync(al, S1l + wr * LDB + k0, LDB);
        wmma::fragment<wmma::matrix_b, 16, 16, 16, bf16, wmma::row_major> bh0, bl0, bh1, bl1;
        wmma::load_matrix_sync(bh0, Qh + k0 * LDB + wc, LDB);
        wmma::load_matrix_sync(bl0, Ql + k0 * LDB + wc, LDB);
        wmma::load_matrix_sync(bh1, Qh + k0 * LDB + wc + 16, LDB);
        wmma::load_matrix_sync(bl1, Ql + k0 * LDB + wc + 16, LDB);
        wmma::mma_sync(acc0, ah, bh0, acc0);
        wmma::mma_sync(acc0, ah, bl0, acc0);
        wmma::mma_sync(acc0, al, bh0, acc0);
        wmma::mma_sync(acc1, ah, bh1, acc1);
        wmma::mma_sync(acc1, ah, bl1, acc1);
        wmma::mma_sync(acc1, al, bh1, acc1);
    }
    __syncthreads();      // all warps done reading Q region
    wmma::store_matrix_sync(stage + wr * LDS + wc, acc0, LDS, wmma::mem_row_major);
    wmma::store_matrix_sync(stage + wr * LDS + wc + 16, acc1, LDS, wmma::mem_row_major);
    CP_WAIT(0);           // T arrived (should be long done)
    __syncthreads();      // stage visible; T visible to all threads

    // epilogue 1: write c, a, c*a
    {
        int r = cBase + lr;
        float* orow = ob + (size_t)r * (4 * HH);
#pragma unroll
        for (int i = 0; i < 4; i++) {
            int col = lcb + i * 16;
            float4 a4 = *(const float4*)(stage + lr * LDS + col);
            float4 cv = cvr[i];
            float4 ca = make_float4(cv.x * a4.x, cv.y * a4.y, cv.z * a4.z, cv.w * a4.w);
            *(float4*)(orow + 0 * HH + hc + col) = cv;
            *(float4*)(orow + 1 * HH + hc + col) = a4;
            *(float4*)(orow + 2 * HH + hc + col) = ca;
        }
    }

    // ---- pass 2: bvec = s1 @ t ----
    wmma::fragment<wmma::accumulator, 16, 16, 16, float> bcc0, bcc1;
    wmma::fill_fragment(bcc0, 0.f);
    wmma::fill_fragment(bcc1, 0.f);
#pragma unroll
    for (int ks = 0; ks < 4; ks++) {
        int k0 = ks * 16;
        wmma::fragment<wmma::matrix_a, 16, 16, 16, bf16, wmma::row_major> ah, al;
        wmma::load_matrix_sync(ah, S1h + wr * LDB + k0, LDB);
        wmma::load_matrix_sync(al, S1l + wr * LDB + k0, LDB);
        wmma::fragment<wmma::matrix_b, 16, 16, 16, bf16, wmma::row_major> bh0, bl0, bh1, bl1;
        wmma::load_matrix_sync(bh0, Th + k0 * LDB + wc, LDB);
        wmma::load_matrix_sync(bl0, Tl + k0 * LDB + wc, LDB);
        wmma::load_matrix_sync(bh1, Th + k0 * LDB + wc + 16, LDB);
        wmma::load_matrix_sync(bl1, Tl + k0 * LDB + wc + 16, LDB);
        wmma::mma_sync(bcc0, ah, bh0, bcc0);
        wmma::mma_sync(bcc0, ah, bl0, bcc0);
        wmma::mma_sync(bcc0, al, bh0, bcc0);
        wmma::mma_sync(bcc1, ah, bh1, bcc1);
        wmma::mma_sync(bcc1, ah, bl1, bcc1);
        wmma::mma_sync(bcc1, al, bh1, bcc1);
    }
    __syncthreads();      // epilogue-1 stage reads done everywhere
    wmma::store_matrix_sync(stage + wr * LDS + wc, bcc0, LDS, wmma::mem_row_major);
    wmma::store_matrix_sync(stage + wr * LDS + wc + 16, bcc1, LDS, wmma::mem_row_major);
    __syncthreads();

    // epilogue 2: write c*bvec
    {
        int r = cBase + lr;
        float* orow = ob + (size_t)r * (4 * HH);
#pragma unroll
        for (int i = 0; i < 4; i++) {
            int col = lcb + i * 16;
            float4 bv4 = *(const float4*)(stage + lr * LDS + col);
            float4 cv = cvr[i];
            float4 cbv = make_float4(cv.x * bv4.x, cv.y * bv4.y, cv.z * bv4.z, cv.w * bv4.w);
            *(float4*)(orow + 3 * HH + hc + col) = cbv;
        }
    }
}

extern "C" void kernel_launch(void* const* d_in, const int* in_sizes, int n_in,
                              void* d_out, int out_size) {
    (void)in_sizes; (void)n_in; (void)out_size;
    const float* c      = (const float*)d_in[0];
    const float* q      = (const float*)d_in[1];
    const int*   c_mask = (const int*)d_in[2];
    const int*   q_mask = (const int*)d_in[3];
    const float* W      = (const float*)d_in[4];
    const float* bias   = (const float*)d_in[5];
    float* out = (float*)d_out;

    const int FINAL_SMEM = 6 * 64 * LDB * (int)sizeof(bf16);   // 61440
    cudaFuncSetAttribute(final_kernel, cudaFuncAttributeMaxDynamicSharedMemorySize, FINAL_SMEM);

    bq_kernel       <<<128, 256>>>(q, bias);
    split_all_kernel<<<7488, 256>>>(q, c, W);
    qp_gemm         <<<dim3(12, 16), 256>>>();
    s_gemm          <<<dim3(8, 16), 256>>>(q_mask);
    colexp_kernel   <<<dim3(16, 4), 256>>>(c_mask);
    t_gemm          <<<dim3(12, 16), 256>>>();
    final_kernel    <<<dim3(8, 16, 12), 256, FINAL_SMEM>>>(c, out);
}